// round 2
// baseline (speedup 1.0000x reference)
#include <cuda_runtime.h>
#include <cuda_bf16.h>
#include <math.h>
#include <stdint.h>

// ---------------- problem constants ----------------
#define BATCH 2
#define SEQL 4096
#define DMODEL 512
#define DSTATE 64
#define DCONV 4
#define HEADDIM 64
#define DINNER 1024
#define NHEADS 16
#define CONVDIM 1152          // DINNER + 2*DSTATE
#define DPROJ 2192            // 2*DINNER + 2*DSTATE + NHEADS
#define DPROJ_PAD 2304        // padded to multiple of 128
#define ROWS (BATCH*SEQL)     // 8192
#define DFF 2048
#define EPS 1e-5f

// ---------------- scratch (static device mem; no allocations) ----------------
__device__ float g_xn   [(size_t)ROWS*DMODEL];
__device__ float g_inw  [(size_t)DMODEL*DPROJ_PAD];
__device__ float g_zx   [(size_t)ROWS*DPROJ_PAD];
__device__ float g_conv [(size_t)BATCH*2*SEQL*CONVDIM];   // [b,d,s,c] silu(conv)
__device__ float g_dt   [(size_t)BATCH*2*SEQL*NHEADS];
__device__ float g_dA   [(size_t)BATCH*2*SEQL*NHEADS];
__device__ float g_y    [(size_t)BATCH*2*SEQL*DINNER];    // indexed by ORIGINAL t
__device__ float g_g    [(size_t)ROWS*DINNER];            // combined gated+rmsnormed
__device__ float g_mid  [(size_t)ROWS*DMODEL];
__device__ float g_m    [(size_t)ROWS*DMODEL];
__device__ float g_ff1  [(size_t)ROWS*DFF];

// ---------------- helpers ----------------
__device__ __forceinline__ float siluf(float x){ return x / (1.f + __expf(-x)); }

__device__ __forceinline__ void cp16(void* smem, const void* g){
    unsigned a = (unsigned)__cvta_generic_to_shared(smem);
    asm volatile("cp.async.cg.shared.global [%0], [%1], 16;\n" :: "r"(a), "l"(g));
}
__device__ __forceinline__ void cp4(void* smem, const void* g){
    unsigned a = (unsigned)__cvta_generic_to_shared(smem);
    asm volatile("cp.async.ca.shared.global [%0], [%1], 4;\n" :: "r"(a), "l"(g));
}

// ---------------- pad in_w to 2304 cols ----------------
__global__ void pad_inw_kernel(const float* __restrict__ w){
    size_t i = (size_t)blockIdx.x*blockDim.x + threadIdx.x;
    if (i >= (size_t)DMODEL*DPROJ_PAD) return;
    int c = (int)(i % DPROJ_PAD); int r = (int)(i / DPROJ_PAD);
    g_inw[i] = (c < DPROJ) ? w[(size_t)r*DPROJ + c] : 0.f;
}

// ---------------- layernorm (warp per 512-row) ----------------
__global__ void ln_kernel(const float* __restrict__ x, const float* __restrict__ w,
                          const float* __restrict__ b, float* __restrict__ out){
    int row = blockIdx.x*(blockDim.x>>5) + (threadIdx.x>>5);
    int lane = threadIdx.x & 31;
    if (row >= ROWS) return;
    const float* xr = x + (size_t)row*DMODEL;
    float v[16]; float s = 0.f;
    #pragma unroll
    for (int i=0;i<16;i++){ v[i] = xr[lane + 32*i]; s += v[i]; }
    #pragma unroll
    for (int o=16;o;o>>=1) s += __shfl_xor_sync(0xffffffffu, s, o);
    float mu = s * (1.f/DMODEL);
    float s2 = 0.f;
    #pragma unroll
    for (int i=0;i<16;i++){ float d = v[i]-mu; s2 += d*d; }
    #pragma unroll
    for (int o=16;o;o>>=1) s2 += __shfl_xor_sync(0xffffffffu, s2, o);
    float inv = rsqrtf(s2*(1.f/DMODEL) + EPS);
    float* orow = out + (size_t)row*DMODEL;
    #pragma unroll
    for (int i=0;i<16;i++){
        int c = lane + 32*i;
        orow[c] = (v[i]-mu)*inv*w[c] + b[c];
    }
}

// ---------------- SGEMM 128x128x8, TM=TN=8, 256 threads ----------------
// EPI: 0 none, 1 bias+gelu(exact), 2 bias+residual
template<int EPI>
__global__ __launch_bounds__(256) void sgemm_kernel(
    const float* __restrict__ A, const float* __restrict__ B, float* __restrict__ C,
    int M, int N, int K, const float* __restrict__ bias, const float* __restrict__ res)
{
    __shared__ float As[8][128];
    __shared__ float Bs[8][128];
    int tid = threadIdx.x;
    int bm = blockIdx.y * 128, bn = blockIdx.x * 128;
    int tx = tid & 15, ty = tid >> 4;
    int arow = tid >> 1, acol = (tid & 1) * 4;
    int brow = tid >> 5, bcol = (tid & 31) * 4;
    const float* Aptr = A + (size_t)(bm + arow)*K + acol;
    const float* Bptr = B + (size_t)brow*N + bn + bcol;
    float acc[8][8];
    #pragma unroll
    for (int i=0;i<8;i++)
        #pragma unroll
        for (int j=0;j<8;j++) acc[i][j] = 0.f;

    for (int k0 = 0; k0 < K; k0 += 8){
        float4 av = *(const float4*)(Aptr + k0);
        float4 bv = *(const float4*)(Bptr + (size_t)k0*N);
        As[acol+0][arow] = av.x; As[acol+1][arow] = av.y;
        As[acol+2][arow] = av.z; As[acol+3][arow] = av.w;
        *(float4*)&Bs[brow][bcol] = bv;
        __syncthreads();
        #pragma unroll
        for (int k=0;k<8;k++){
            float ra[8], rb[8];
            #pragma unroll
            for (int i=0;i<8;i++) ra[i] = As[k][ty*8+i];
            #pragma unroll
            for (int j=0;j<8;j++) rb[j] = Bs[k][tx*8+j];
            #pragma unroll
            for (int i=0;i<8;i++)
                #pragma unroll
                for (int j=0;j<8;j++) acc[i][j] += ra[i]*rb[j];
        }
        __syncthreads();
    }
    #pragma unroll
    for (int i=0;i<8;i++){
        int row = bm + ty*8 + i;
        float* Cr = C + (size_t)row*N + bn + tx*8;
        #pragma unroll
        for (int j=0;j<8;j++){
            float v = acc[i][j];
            int col = bn + tx*8 + j;
            if (EPI == 1){
                v += bias[col];
                v = 0.5f*v*(1.f + erff(v*0.70710678118654752f));
            } else if (EPI == 2){
                v += bias[col] + res[(size_t)row*N + col];
            }
            Cr[j] = v;
        }
    }
}

// ---------------- dt / dA precompute ----------------
__global__ void dtda_kernel(const float* __restrict__ dt_bias, const float* __restrict__ A_log){
    size_t i = (size_t)blockIdx.x*blockDim.x + threadIdx.x;
    size_t total = (size_t)BATCH*2*SEQL*NHEADS;
    if (i >= total) return;
    int h = (int)(i % NHEADS);
    size_t r = i / NHEADS;
    int s = (int)(r % SEQL);
    int bd = (int)(r / SEQL);
    int d = bd & 1, b = bd >> 1;
    int t = d ? (SEQL-1-s) : s;
    float raw = g_zx[((size_t)(b*SEQL+t))*DPROJ_PAD + (2*DINNER + 2*DSTATE - DINNER) + 0];
    // dt raw channel = 1024 (z) + 1152 (xBC) + h = 2176 + h
    raw = g_zx[((size_t)(b*SEQL+t))*DPROJ_PAD + 2176 + h] + dt_bias[h];
    float dt = (raw > 20.f) ? raw : log1pf(__expf(raw));
    g_dt[i] = dt;
    g_dA[i] = __expf(-__expf(A_log[h]) * dt);
}

// ---------------- depthwise causal conv + silu (per direction) ----------------
__global__ void conv_kernel(const float* __restrict__ cw, const float* __restrict__ cb){
    size_t i = (size_t)blockIdx.x*blockDim.x + threadIdx.x;
    size_t total = (size_t)BATCH*2*SEQL*CONVDIM;
    if (i >= total) return;
    int c = (int)(i % CONVDIM);
    size_t r = i / CONVDIM;
    int s = (int)(r % SEQL);
    int bd = (int)(r / SEQL);
    int d = bd & 1, b = bd >> 1;
    float acc = cb[c];
    #pragma unroll
    for (int k=0;k<DCONV;k++){
        int u = s - (DCONV-1) + k;
        if (u >= 0){
            int t = d ? (SEQL-1-u) : u;
            acc += cw[k*CONVDIM + c] * g_zx[((size_t)(b*SEQL+t))*DPROJ_PAD + DINNER + c];
        }
    }
    g_conv[i] = siluf(acc);
}

// ---------------- selective scan: 64 CTAs (b,d,h), state in registers ----------------
#define CHUNK 16
#define NCHUNK (SEQL/CHUNK)

__global__ __launch_bounds__(256) void scan_kernel(const float* __restrict__ Dh){
    int bx = blockIdx.x;            // 0..63
    int h = bx & 15, d = (bx >> 4) & 1, b = bx >> 5;
    int tid = threadIdx.x;
    int p = tid >> 2, q = tid & 3;  // p: headdim row 0..63, q: state quarter

    __shared__ float buf[2][CHUNK][192];   // [xh 64][B 64][C 64]
    __shared__ float sdt[2][CHUNK], sdA[2][CHUNK];

    const float* base = g_conv + ((size_t)(b*2+d))*SEQL*CONVDIM;
    const float* dtb  = g_dt  + ((size_t)(b*2+d))*SEQL*NHEADS + h;
    const float* dab  = g_dA  + ((size_t)(b*2+d))*SEQL*NHEADS + h;
    float* ybase = g_y + ((size_t)(b*2+d))*SEQL*DINNER;

    float hreg[16];
    #pragma unroll
    for (int i=0;i<16;i++) hreg[i] = 0.f;
    float Dhh = Dh[h];

    auto issue = [&](int c, int sbuf){
        int s0 = c*CHUNK;
        #pragma unroll
        for (int rr=0;rr<3;rr++){
            int j = tid + rr*256;        // 0..767
            int step = j / 48;
            int seg = j % 48;
            int off = seg*4;             // float offset within 192
            const float* src;
            const float* rowp = base + (size_t)(s0+step)*CONVDIM;
            if (off < 64)       src = rowp + h*HEADDIM + off;
            else if (off < 128) src = rowp + DINNER + (off-64);
            else                src = rowp + DINNER + DSTATE + (off-128);
            cp16(&buf[sbuf][step][off], src);
        }
        if (tid < CHUNK)            cp4(&sdt[sbuf][tid],        dtb + (size_t)(s0+tid)*NHEADS);
        else if (tid < 2*CHUNK)     cp4(&sdA[sbuf][tid-CHUNK],  dab + (size_t)(s0+tid-CHUNK)*NHEADS);
        asm volatile("cp.async.commit_group;\n");
    };

    issue(0, 0);
    for (int c=0;c<NCHUNK;c++){
        int cur = c & 1, nxt = cur ^ 1;
        if (c+1 < NCHUNK){
            issue(c+1, nxt);
            asm volatile("cp.async.wait_group 1;\n");
        } else {
            asm volatile("cp.async.wait_group 0;\n");
        }
        __syncthreads();
        #pragma unroll 4
        for (int k=0;k<CHUNK;k++){
            const float* row = buf[cur][k];
            float dt = sdt[cur][k], dA = sdA[cur][k];
            float xh = row[p];
            float dtx = dt*xh;
            const float* Bp = row + 64 + q*16;
            const float* Cp = row + 128 + q*16;
            float acc = 0.f;
            #pragma unroll
            for (int i=0;i<16;i++){
                hreg[i] = hreg[i]*dA + dtx*Bp[i];
                acc += hreg[i]*Cp[i];
            }
            acc += __shfl_xor_sync(0xffffffffu, acc, 1);
            acc += __shfl_xor_sync(0xffffffffu, acc, 2);
            if (q == 0){
                int s = c*CHUNK + k;
                int t = d ? (SEQL-1-s) : s;
                ybase[(size_t)t*DINNER + h*HEADDIM + p] = acc + Dhh*xh;
            }
        }
        __syncthreads();
    }
}

// ---------------- gate (silu(z)), per-direction RMS norm, combine ----------------
__global__ void gate_kernel(const float* __restrict__ mw){
    int row = blockIdx.x;            // 0..8191 (= b*SEQL + t)
    int b = row >> 12, t = row & (SEQL-1);
    const float* z  = g_zx + (size_t)row*DPROJ_PAD;           // cols 0..1024
    const float* y0 = g_y + ((size_t)(b*2+0)*SEQL + t)*DINNER;
    const float* y1 = g_y + ((size_t)(b*2+1)*SEQL + t)*DINNER;
    float g0[4], g1[4];
    float ss0 = 0.f, ss1 = 0.f;
    #pragma unroll
    for (int j=0;j<4;j++){
        int c = threadIdx.x + j*256;
        float zz = z[c];
        float sz = siluf(zz);
        g0[j] = y0[c]*sz; g1[j] = y1[c]*sz;
        ss0 += g0[j]*g0[j]; ss1 += g1[j]*g1[j];
    }
    #pragma unroll
    for (int o=16;o;o>>=1){
        ss0 += __shfl_xor_sync(0xffffffffu, ss0, o);
        ss1 += __shfl_xor_sync(0xffffffffu, ss1, o);
    }
    __shared__ float red[16];
    int wid = threadIdx.x >> 5, lane = threadIdx.x & 31;
    if (lane == 0){ red[wid] = ss0; red[8+wid] = ss1; }
    __syncthreads();
    if (threadIdx.x == 0){
        float a=0.f, bb=0.f;
        #pragma unroll
        for (int w=0;w<8;w++){ a += red[w]; bb += red[8+w]; }
        red[0] = a; red[8] = bb;
    }
    __syncthreads();
    float r0 = rsqrtf(red[0]*(1.f/DINNER) + EPS);
    float r1 = rsqrtf(red[8]*(1.f/DINNER) + EPS);
    float* go = g_g + (size_t)row*DINNER;
    #pragma unroll
    for (int j=0;j<4;j++){
        int c = threadIdx.x + j*256;
        go[c] = (g0[j]*r0 + g1[j]*r1) * mw[c];
    }
}

// ---------------- launch ----------------
extern "C" void kernel_launch(void* const* d_in, const int* in_sizes, int n_in,
                              void* d_out, int out_size)
{
    const float* x        = (const float*)d_in[0];
    const float* nin_w    = (const float*)d_in[1];
    const float* nin_b    = (const float*)d_in[2];
    const float* nout_w   = (const float*)d_in[3];
    const float* nout_b   = (const float*)d_in[4];
    const float* in_w     = (const float*)d_in[5];
    const float* conv_w   = (const float*)d_in[6];
    const float* conv_b   = (const float*)d_in[7];
    const float* dt_bias  = (const float*)d_in[8];
    const float* A_log    = (const float*)d_in[9];
    const float* D_h      = (const float*)d_in[10];
    const float* mnorm_w  = (const float*)d_in[11];
    const float* out_w    = (const float*)d_in[12];
    const float* ff_w1    = (const float*)d_in[13];
    const float* ff_b1    = (const float*)d_in[14];
    const float* ff_w2    = (const float*)d_in[15];
    const float* ff_b2    = (const float*)d_in[16];
    float* out = (float*)d_out;

    float *p_xn, *p_inw, *p_zx, *p_g, *p_mid, *p_m, *p_ff1;
    cudaGetSymbolAddress((void**)&p_xn,  g_xn);
    cudaGetSymbolAddress((void**)&p_inw, g_inw);
    cudaGetSymbolAddress((void**)&p_zx,  g_zx);
    cudaGetSymbolAddress((void**)&p_g,   g_g);
    cudaGetSymbolAddress((void**)&p_mid, g_mid);
    cudaGetSymbolAddress((void**)&p_m,   g_m);
    cudaGetSymbolAddress((void**)&p_ff1, g_ff1);

    // 1. pad in_w
    {
        size_t tot = (size_t)DMODEL*DPROJ_PAD;
        pad_inw_kernel<<<(unsigned)((tot+255)/256), 256>>>(in_w);
    }
    // 2. layernorm in
    ln_kernel<<<ROWS/8, 256>>>(x, nin_w, nin_b, p_xn);
    // 3. in-proj GEMM: xn[8192,512] @ inw_pad[512,2304]
    {
        dim3 grid(DPROJ_PAD/128, ROWS/128);
        sgemm_kernel<0><<<grid, 256>>>(p_xn, p_inw, p_zx, ROWS, DPROJ_PAD, DMODEL, nullptr, nullptr);
    }
    // 4. dt/dA
    {
        size_t tot = (size_t)BATCH*2*SEQL*NHEADS;
        dtda_kernel<<<(unsigned)((tot+255)/256), 256>>>(dt_bias, A_log);
    }
    // 5. conv+silu (both directions)
    {
        size_t tot = (size_t)BATCH*2*SEQL*CONVDIM;
        conv_kernel<<<(unsigned)((tot+255)/256), 256>>>(conv_w, conv_b);
    }
    // 6. selective scan
    scan_kernel<<<BATCH*2*NHEADS, 256>>>(D_h);
    // 7. gate + per-dir rmsnorm + combine
    gate_kernel<<<ROWS, 256>>>(mnorm_w);
    // 8. out-proj GEMM: g[8192,1024] @ out_w[1024,512]
    {
        dim3 grid(DMODEL/128, ROWS/128);
        sgemm_kernel<0><<<grid, 256>>>(p_g, out_w, p_mid, ROWS, DMODEL, DINNER, nullptr, nullptr);
    }
    // 9. layernorm out
    ln_kernel<<<ROWS/8, 256>>>(p_mid, nout_w, nout_b, p_m);
    // 10. FF1 + gelu: m[8192,512] @ ff_w1[512,2048]
    {
        dim3 grid(DFF/128, ROWS/128);
        sgemm_kernel<1><<<grid, 256>>>(p_m, ff_w1, p_ff1, ROWS, DFF, DMODEL, ff_b1, nullptr);
    }
    // 11. FF2 + bias + residual(x): ff1[8192,2048] @ ff_w2[2048,512] + b2 + x
    {
        dim3 grid(DMODEL/128, ROWS/128);
        sgemm_kernel<2><<<grid, 256>>>(p_ff1, ff_w2, out, ROWS, DMODEL, DFF, ff_b2, x);
    }
}

// round 7
// speedup vs baseline: 1.4502x; 1.4502x over previous
#include <cuda_runtime.h>
#include <cuda_bf16.h>
#include <math.h>
#include <stdint.h>

// ---------------- problem constants ----------------
#define BATCH 2
#define SEQL 4096
#define DMODEL 512
#define DSTATE 64
#define DCONV 4
#define HEADDIM 64
#define DINNER 1024
#define NHEADS 16
#define CONVDIM 1152          // DINNER + 2*DSTATE
#define DPROJ 2192            // 2*DINNER + 2*DSTATE + NHEADS
#define DPROJ_PAD 2304        // padded to multiple of 128
#define ROWS (BATCH*SEQL)     // 8192
#define DFF 2048
#define EPS 1e-5f

// ---------------- scratch (static device mem; no allocations) ----------------
__device__ float g_xn   [(size_t)ROWS*DMODEL];
__device__ float g_zx   [(size_t)ROWS*DPROJ_PAD];
__device__ float g_conv [(size_t)BATCH*2*SEQL*CONVDIM];   // [b,d,s,c] silu(conv)
__device__ float g_dt   [(size_t)BATCH*2*SEQL*NHEADS];
__device__ float g_dA   [(size_t)BATCH*2*SEQL*NHEADS];
__device__ float g_y    [(size_t)BATCH*2*SEQL*DINNER];    // indexed by ORIGINAL t
__device__ float g_g    [(size_t)ROWS*DINNER];            // combined gated+rmsnormed
__device__ float g_mid  [(size_t)ROWS*DMODEL];
__device__ float g_m    [(size_t)ROWS*DMODEL];
__device__ float g_ff1  [(size_t)ROWS*DFF];
// transposed weights [N, K] K-major (tf32-rounded)
__device__ float g_inwT [(size_t)DPROJ_PAD*DMODEL];
__device__ float g_outwT[(size_t)DMODEL*DINNER];
__device__ float g_ff1T [(size_t)DFF*DMODEL];
__device__ float g_ff2T [(size_t)DMODEL*DFF];

// ---------------- helpers ----------------
__device__ __forceinline__ float siluf(float x){ return x / (1.f + __expf(-x)); }

__device__ __forceinline__ float to_tf32(float x){
    uint32_t u;
    asm("cvt.rna.tf32.f32 %0, %1;" : "=r"(u) : "f"(x));
    return __uint_as_float(u);
}

__device__ __forceinline__ uint32_t smem_u32(const void* p){
    uint32_t a;
    asm("{ .reg .u64 t; cvta.to.shared.u64 t, %1; cvt.u32.u64 %0, t; }" : "=r"(a) : "l"(p));
    return a;
}
__device__ __forceinline__ void cp16(void* smem, const void* g){
    unsigned a = smem_u32(smem);
    asm volatile("cp.async.cg.shared.global [%0], [%1], 16;\n" :: "r"(a), "l"(g));
}
__device__ __forceinline__ void cp4(void* smem, const void* g){
    unsigned a = smem_u32(smem);
    asm volatile("cp.async.ca.shared.global [%0], [%1], 4;\n" :: "r"(a), "l"(g));
}

__device__ __forceinline__ void mma_tf32(float* d, const uint32_t* a, const uint32_t* b){
    asm volatile(
        "mma.sync.aligned.m16n8k8.row.col.f32.tf32.tf32.f32 "
        "{%0,%1,%2,%3}, {%4,%5,%6,%7}, {%8,%9}, {%0,%1,%2,%3};"
        : "+f"(d[0]), "+f"(d[1]), "+f"(d[2]), "+f"(d[3])
        : "r"(a[0]), "r"(a[1]), "r"(a[2]), "r"(a[3]), "r"(b[0]), "r"(b[1]));
}

// swizzled smem index for [row][k] tile with 16 floats per row
__device__ __forceinline__ int swi(int row, int k){
    return row*16 + ((((k>>2) ^ row) & 3) << 2) + (k & 3);
}

// ---------------- tiled transpose w/ zero pad + tf32 rounding ----------------
__global__ void transpose_pad_kernel(const float* __restrict__ in, float* __restrict__ out,
                                     int K, int N0, int Npad){
    __shared__ float t[32][33];
    int kb = blockIdx.x*32, nb = blockIdx.y*32;
    int x = threadIdx.x, y = threadIdx.y;   // 32 x 8
    #pragma unroll
    for (int i=0;i<32;i+=8){
        int k = kb + y + i, n = nb + x;
        t[y+i][x] = (n < N0) ? to_tf32(in[(size_t)k*N0 + n]) : 0.f;
    }
    __syncthreads();
    #pragma unroll
    for (int i=0;i<32;i+=8){
        int n = nb + y + i, k = kb + x;
        out[(size_t)n*K + k] = t[x][y+i];
    }
}

// ---------------- layernorm (warp per 512-row), output tf32-rounded ----------------
__global__ void ln_kernel(const float* __restrict__ x, const float* __restrict__ w,
                          const float* __restrict__ b, float* __restrict__ out){
    int row = blockIdx.x*(blockDim.x>>5) + (threadIdx.x>>5);
    int lane = threadIdx.x & 31;
    if (row >= ROWS) return;
    const float* xr = x + (size_t)row*DMODEL;
    float v[16]; float s = 0.f;
    #pragma unroll
    for (int i=0;i<16;i++){ v[i] = xr[lane + 32*i]; s += v[i]; }
    #pragma unroll
    for (int o=16;o;o>>=1) s += __shfl_xor_sync(0xffffffffu, s, o);
    float mu = s * (1.f/DMODEL);
    float s2 = 0.f;
    #pragma unroll
    for (int i=0;i<16;i++){ float d = v[i]-mu; s2 += d*d; }
    #pragma unroll
    for (int o=16;o;o>>=1) s2 += __shfl_xor_sync(0xffffffffu, s2, o);
    float inv = rsqrtf(s2*(1.f/DMODEL) + EPS);
    float* orow = out + (size_t)row*DMODEL;
    #pragma unroll
    for (int i=0;i<16;i++){
        int c = lane + 32*i;
        orow[c] = to_tf32((v[i]-mu)*inv*w[c] + b[c]);
    }
}

// ---------------- tf32 mma.sync GEMM: C[M,N] = A[M,K] @ B[N,K]^T ----------------
// BM=128, BN=128, BK=16, 256 threads (8 warps, 4x2, warp tile 32x64), double-buffered
// EPI: 0 none, 1 bias+gelu(exact) [tf32-rounded out], 2 bias+residual
template<int EPI>
__global__ __launch_bounds__(256) void mma_gemm(
    const float* __restrict__ A, const float* __restrict__ Bw, float* __restrict__ C,
    int K, int N, const float* __restrict__ bias, const float* __restrict__ res)
{
    __shared__ float As[2][128*16];
    __shared__ float Bs[2][128*16];
    int tid = threadIdx.x, lane = tid & 31, wid = tid >> 5;
    int bm = blockIdx.y * 128, bn = blockIdx.x * 128;
    int wm = (wid >> 1) * 32, wn = (wid & 1) * 64;
    int grp = lane >> 2, tig = lane & 3;

    float acc[2][8][4];
    #pragma unroll
    for (int mi=0;mi<2;mi++)
        #pragma unroll
        for (int ni=0;ni<8;ni++)
            #pragma unroll
            for (int u=0;u<4;u++) acc[mi][ni][u] = 0.f;

    auto load = [&](int st, int k0){
        #pragma unroll
        for (int i=0;i<2;i++){
            int q = tid + i*256;            // 0..511
            int row = q >> 2, c = q & 3;
            int dc = (c ^ row) & 3;
            cp16(&As[st][row*16 + dc*4], A + (size_t)(bm+row)*K + k0 + c*4);
        }
        #pragma unroll
        for (int i=0;i<2;i++){
            int q = tid + i*256;
            int row = q >> 2, c = q & 3;
            int dc = (c ^ row) & 3;
            cp16(&Bs[st][row*16 + dc*4], Bw + (size_t)(bn+row)*K + k0 + c*4);
        }
        asm volatile("cp.async.commit_group;\n");
    };

    int nk = K >> 4;
    load(0, 0);
    for (int kt = 0; kt < nk; kt++){
        int cur = kt & 1, nxt = cur ^ 1;
        if (kt + 1 < nk){
            load(nxt, (kt+1) << 4);
            asm volatile("cp.async.wait_group 1;\n");
        } else {
            asm volatile("cp.async.wait_group 0;\n");
        }
        __syncthreads();
        const float* as = As[cur];
        const float* bs = Bs[cur];
        #pragma unroll
        for (int kk = 0; kk < 16; kk += 8){
            uint32_t af[2][4], bf[8][2];
            #pragma unroll
            for (int mi=0;mi<2;mi++){
                int r = wm + mi*16 + grp;
                af[mi][0] = __float_as_uint(as[swi(r,   kk+tig)]);
                af[mi][1] = __float_as_uint(as[swi(r+8, kk+tig)]);
                af[mi][2] = __float_as_uint(as[swi(r,   kk+tig+4)]);
                af[mi][3] = __float_as_uint(as[swi(r+8, kk+tig+4)]);
            }
            #pragma unroll
            for (int ni=0;ni<8;ni++){
                int c0 = wn + ni*8 + grp;
                bf[ni][0] = __float_as_uint(bs[swi(c0, kk+tig)]);
                bf[ni][1] = __float_as_uint(bs[swi(c0, kk+tig+4)]);
            }
            #pragma unroll
            for (int mi=0;mi<2;mi++)
                #pragma unroll
                for (int ni=0;ni<8;ni++)
                    mma_tf32(acc[mi][ni], af[mi], bf[ni]);
        }
        __syncthreads();
    }

    // epilogue: c0,c1 -> row grp, cols tig*2, tig*2+1 ; c2,c3 -> row grp+8
    #pragma unroll
    for (int mi=0;mi<2;mi++){
        #pragma unroll
        for (int half=0; half<2; half++){
            int row = bm + wm + mi*16 + grp + half*8;
            #pragma unroll
            for (int ni=0;ni<8;ni++){
                int col = bn + wn + ni*8 + tig*2;
                float v0 = acc[mi][ni][half*2+0];
                float v1 = acc[mi][ni][half*2+1];
                if (EPI == 1){
                    v0 += bias[col];   v1 += bias[col+1];
                    v0 = 0.5f*v0*(1.f + erff(v0*0.70710678118654752f));
                    v1 = 0.5f*v1*(1.f + erff(v1*0.70710678118654752f));
                    v0 = to_tf32(v0); v1 = to_tf32(v1);
                } else if (EPI == 2){
                    v0 += bias[col]   + res[(size_t)row*N + col];
                    v1 += bias[col+1] + res[(size_t)row*N + col+1];
                }
                float2 v; v.x = v0; v.y = v1;
                *(float2*)(C + (size_t)row*N + col) = v;
            }
        }
    }
}

// ---------------- exact fp32 dt / dA from xn (16 cols of in-proj) ----------------
__global__ void dtda_kernel(const float* __restrict__ in_w,
                            const float* __restrict__ dt_bias,
                            const float* __restrict__ A_log){
    // 256 threads = 16 rows x 16 heads
    int row = blockIdx.x*16 + (threadIdx.x >> 4);
    int h = threadIdx.x & 15;
    const float* xr = g_xn + (size_t)row*DMODEL;
    const float* wc = in_w + 2176 + h;   // column 2176+h, stride DPROJ
    float acc = dt_bias[h];
    #pragma unroll 8
    for (int k = 0; k < DMODEL; k++)
        acc += xr[k] * wc[(size_t)k*DPROJ];
    float dt = (acc > 20.f) ? acc : log1pf(__expf(acc));
    float dA = __expf(-__expf(A_log[h]) * dt);
    int b = row >> 12, t = row & (SEQL-1);
    size_t i0 = ((size_t)(b*2+0)*SEQL + t)*NHEADS + h;
    size_t i1 = ((size_t)(b*2+1)*SEQL + (SEQL-1-t))*NHEADS + h;
    g_dt[i0] = dt; g_dA[i0] = dA;
    g_dt[i1] = dt; g_dA[i1] = dA;
}

// ---------------- depthwise causal conv + silu (per direction) ----------------
__global__ void conv_kernel(const float* __restrict__ cw, const float* __restrict__ cb){
    size_t i = (size_t)blockIdx.x*blockDim.x + threadIdx.x;
    size_t total = (size_t)BATCH*2*SEQL*CONVDIM;
    if (i >= total) return;
    int c = (int)(i % CONVDIM);
    size_t r = i / CONVDIM;
    int s = (int)(r % SEQL);
    int bd = (int)(r / SEQL);
    int d = bd & 1, b = bd >> 1;
    float acc = cb[c];
    #pragma unroll
    for (int k=0;k<DCONV;k++){
        int u = s - (DCONV-1) + k;
        if (u >= 0){
            int t = d ? (SEQL-1-u) : u;
            acc += cw[k*CONVDIM + c] * g_zx[((size_t)(b*SEQL+t))*DPROJ_PAD + DINNER + c];
        }
    }
    g_conv[i] = siluf(acc);
}

// ---------------- selective scan: 64 CTAs (b,d,h), state in registers ----------------
#define CHUNK 16
#define NCHUNK (SEQL/CHUNK)

__global__ __launch_bounds__(256) void scan_kernel(const float* __restrict__ Dh){
    int bx = blockIdx.x;            // 0..63
    int h = bx & 15, d = (bx >> 4) & 1, b = bx >> 5;
    int tid = threadIdx.x;
    int p = tid >> 2, q = tid & 3;  // p: headdim row 0..63, q: state quarter

    __shared__ float buf[2][CHUNK][192];   // [xh 64][B 64][C 64]
    __shared__ float sdt[2][CHUNK], sdA[2][CHUNK];

    const float* base = g_conv + ((size_t)(b*2+d))*SEQL*CONVDIM;
    const float* dtb  = g_dt  + ((size_t)(b*2+d))*SEQL*NHEADS + h;
    const float* dab  = g_dA  + ((size_t)(b*2+d))*SEQL*NHEADS + h;
    float* ybase = g_y + ((size_t)(b*2+d))*SEQL*DINNER;

    float hreg[16];
    #pragma unroll
    for (int i=0;i<16;i++) hreg[i] = 0.f;
    float Dhh = Dh[h];

    auto issue = [&](int c, int sbuf){
        int s0 = c*CHUNK;
        #pragma unroll
        for (int rr=0;rr<3;rr++){
            int j = tid + rr*256;        // 0..767
            int step = j / 48;
            int seg = j % 48;
            int off = seg*4;             // float offset within 192
            const float* src;
            const float* rowp = base + (size_t)(s0+step)*CONVDIM;
            if (off < 64)       src = rowp + h*HEADDIM + off;
            else if (off < 128) src = rowp + DINNER + (off-64);
            else                src = rowp + DINNER + DSTATE + (off-128);
            cp16(&buf[sbuf][step][off], src);
        }
        if (tid < CHUNK)            cp4(&sdt[sbuf][tid],        dtb + (size_t)(s0+tid)*NHEADS);
        else if (tid < 2*CHUNK)     cp4(&sdA[sbuf][tid-CHUNK],  dab + (size_t)(s0+tid-CHUNK)*NHEADS);
        asm volatile("cp.async.commit_group;\n");
    };

    issue(0, 0);
    for (int c=0;c<NCHUNK;c++){
        int cur = c & 1, nxt = cur ^ 1;
        if (c+1 < NCHUNK){
            issue(c+1, nxt);
            asm volatile("cp.async.wait_group 1;\n");
        } else {
            asm volatile("cp.async.wait_group 0;\n");
        }
        __syncthreads();
        #pragma unroll 4
        for (int k=0;k<CHUNK;k++){
            const float* row = buf[cur][k];
            float dt = sdt[cur][k], dA = sdA[cur][k];
            float xh = row[p];
            float dtx = dt*xh;
            const float4* Bp4 = (const float4*)(row + 64 + q*16);
            const float4* Cp4 = (const float4*)(row + 128 + q*16);
            float bv[16], cv[16];
            #pragma unroll
            for (int v2=0; v2<4; v2++){
                float4 bb = Bp4[v2], cc = Cp4[v2];
                bv[4*v2+0]=bb.x; bv[4*v2+1]=bb.y; bv[4*v2+2]=bb.z; bv[4*v2+3]=bb.w;
                cv[4*v2+0]=cc.x; cv[4*v2+1]=cc.y; cv[4*v2+2]=cc.z; cv[4*v2+3]=cc.w;
            }
            float acc = 0.f;
            #pragma unroll
            for (int i=0;i<16;i++){
                hreg[i] = hreg[i]*dA + dtx*bv[i];
                acc += hreg[i]*cv[i];
            }
            acc += __shfl_xor_sync(0xffffffffu, acc, 1);
            acc += __shfl_xor_sync(0xffffffffu, acc, 2);
            if (q == 0){
                int s = c*CHUNK + k;
                int t = d ? (SEQL-1-s) : s;
                ybase[(size_t)t*DINNER + h*HEADDIM + p] = acc + Dhh*xh;
            }
        }
        __syncthreads();
    }
}

// ---------------- gate (silu(z)), per-direction RMS norm, combine (tf32 out) ----------------
__global__ void gate_kernel(const float* __restrict__ mw){
    int row = blockIdx.x;            // 0..8191 (= b*SEQL + t)
    int b = row >> 12, t = row & (SEQL-1);
    const float* z  = g_zx + (size_t)row*DPROJ_PAD;           // cols 0..1024
    const float* y0 = g_y + ((size_t)(b*2+0)*SEQL + t)*DINNER;
    const float* y1 = g_y + ((size_t)(b*2+1)*SEQL + t)*DINNER;
    float g0[4], g1[4];
    float ss0 = 0.f, ss1 = 0.f;
    #pragma unroll
    for (int j=0;j<4;j++){
        int c = threadIdx.x + j*256;
        float zz = z[c];
        float sz = siluf(zz);
        g0[j] = y0[c]*sz; g1[j] = y1[c]*sz;
        ss0 += g0[j]*g0[j]; ss1 += g1[j]*g1[j];
    }
    #pragma unroll
    for (int o=16;o;o>>=1){
        ss0 += __shfl_xor_sync(0xffffffffu, ss0, o);
        ss1 += __shfl_xor_sync(0xffffffffu, ss1, o);
    }
    __shared__ float red[16];
    int wid = threadIdx.x >> 5, lane = threadIdx.x & 31;
    if (lane == 0){ red[wid] = ss0; red[8+wid] = ss1; }
    __syncthreads();
    if (threadIdx.x == 0){
        float a=0.f, bb=0.f;
        #pragma unroll
        for (int w=0;w<8;w++){ a += red[w]; bb += red[8+w]; }
        red[0] = a; red[8] = bb;
    }
    __syncthreads();
    float r0 = rsqrtf(red[0]*(1.f/DINNER) + EPS);
    float r1 = rsqrtf(red[8]*(1.f/DINNER) + EPS);
    float* go = g_g + (size_t)row*DINNER;
    #pragma unroll
    for (int j=0;j<4;j++){
        int c = threadIdx.x + j*256;
        go[c] = to_tf32((g0[j]*r0 + g1[j]*r1) * mw[c]);
    }
}

// ---------------- launch ----------------
extern "C" void kernel_launch(void* const* d_in, const int* in_sizes, int n_in,
                              void* d_out, int out_size)
{
    const float* x        = (const float*)d_in[0];
    const float* nin_w    = (const float*)d_in[1];
    const float* nin_b    = (const float*)d_in[2];
    const float* nout_w   = (const float*)d_in[3];
    const float* nout_b   = (const float*)d_in[4];
    const float* in_w     = (const float*)d_in[5];
    const float* conv_w   = (const float*)d_in[6];
    const float* conv_b   = (const float*)d_in[7];
    const float* dt_bias  = (const float*)d_in[8];
    const float* A_log    = (const float*)d_in[9];
    const float* D_h      = (const float*)d_in[10];
    const float* mnorm_w  = (const float*)d_in[11];
    const float* out_w    = (const float*)d_in[12];
    const float* ff_w1    = (const float*)d_in[13];
    const float* ff_b1    = (const float*)d_in[14];
    const float* ff_w2    = (const float*)d_in[15];
    const float* ff_b2    = (const float*)d_in[16];
    float* out = (float*)d_out;

    float *p_xn, *p_zx, *p_g, *p_mid, *p_m, *p_ff1;
    float *p_inwT, *p_outwT, *p_ff1T, *p_ff2T;
    cudaGetSymbolAddress((void**)&p_xn,   g_xn);
    cudaGetSymbolAddress((void**)&p_zx,   g_zx);
    cudaGetSymbolAddress((void**)&p_g,    g_g);
    cudaGetSymbolAddress((void**)&p_mid,  g_mid);
    cudaGetSymbolAddress((void**)&p_m,    g_m);
    cudaGetSymbolAddress((void**)&p_ff1,  g_ff1);
    cudaGetSymbolAddress((void**)&p_inwT, g_inwT);
    cudaGetSymbolAddress((void**)&p_outwT,g_outwT);
    cudaGetSymbolAddress((void**)&p_ff1T, g_ff1T);
    cudaGetSymbolAddress((void**)&p_ff2T, g_ff2T);

    dim3 tb32(32, 8);
    // weight transposes: out[n*K+k] = tf32(in[k*N0+n])
    transpose_pad_kernel<<<dim3(DMODEL/32, DPROJ_PAD/32), tb32>>>(in_w,  p_inwT,  DMODEL, DPROJ, DPROJ_PAD);
    transpose_pad_kernel<<<dim3(DINNER/32, DMODEL/32),    tb32>>>(out_w, p_outwT, DINNER, DMODEL, DMODEL);
    transpose_pad_kernel<<<dim3(DMODEL/32, DFF/32),       tb32>>>(ff_w1, p_ff1T,  DMODEL, DFF, DFF);
    transpose_pad_kernel<<<dim3(DFF/32, DMODEL/32),       tb32>>>(ff_w2, p_ff2T,  DFF, DMODEL, DMODEL);

    // layernorm in (tf32-rounded output)
    ln_kernel<<<ROWS/8, 256>>>(x, nin_w, nin_b, p_xn);

    // in-proj: xn[8192,512] @ inwT[2304,512]^T -> zx[8192,2304]
    mma_gemm<0><<<dim3(DPROJ_PAD/128, ROWS/128), 256>>>(
        p_xn, p_inwT, p_zx, DMODEL, DPROJ_PAD, nullptr, nullptr);

    // exact fp32 dt/dA from xn
    dtda_kernel<<<ROWS/16, 256>>>(in_w, dt_bias, A_log);

    // conv + silu (both directions)
    {
        size_t tot = (size_t)BATCH*2*SEQL*CONVDIM;
        conv_kernel<<<(unsigned)((tot+255)/256), 256>>>(conv_w, conv_b);
    }
    // selective scan
    scan_kernel<<<BATCH*2*NHEADS, 256>>>(D_h);
    // gate + per-dir rmsnorm + combine (tf32 out)
    gate_kernel<<<ROWS, 256>>>(mnorm_w);

    // out-proj: g[8192,1024] @ outwT[512,1024]^T -> mid[8192,512]
    mma_gemm<0><<<dim3(DMODEL/128, ROWS/128), 256>>>(
        p_g, p_outwT, p_mid, DINNER, DMODEL, nullptr, nullptr);

    // layernorm out (tf32-rounded output)
    ln_kernel<<<ROWS/8, 256>>>(p_mid, nout_w, nout_b, p_m);

    // FF1 + gelu: m[8192,512] @ ff1T[2048,512]^T -> ff1[8192,2048] (tf32 out)
    mma_gemm<1><<<dim3(DFF/128, ROWS/128), 256>>>(
        p_m, p_ff1T, p_ff1, DMODEL, DFF, ff_b1, nullptr);

    // FF2 + bias + residual(x): ff1[8192,2048] @ ff2T[512,2048]^T -> out[8192,512]
    mma_gemm<2><<<dim3(DMODEL/128, ROWS/128), 256>>>(
        p_ff1, p_ff2T, out, DFF, DMODEL, ff_b2, x);
}

// round 11
// speedup vs baseline: 1.4832x; 1.0227x over previous
#include <cuda_runtime.h>
#include <cuda_bf16.h>
#include <math.h>
#include <stdint.h>

// ---------------- problem constants ----------------
#define BATCH 2
#define SEQL 4096
#define DMODEL 512
#define DSTATE 64
#define DCONV 4
#define HEADDIM 64
#define DINNER 1024
#define NHEADS 16
#define CONVDIM 1152          // DINNER + 2*DSTATE
#define DPROJ 2192            // 2*DINNER + 2*DSTATE + NHEADS
#define DPROJ_PAD 2304        // padded to multiple of 128
#define ROWS (BATCH*SEQL)     // 8192
#define DFF 2048
#define EPS 1e-5f

// ---------------- scratch (static device mem; no allocations) ----------------
__device__ float g_xn   [(size_t)ROWS*DMODEL];
__device__ float g_zx   [(size_t)ROWS*DPROJ_PAD];
__device__ float g_conv [(size_t)BATCH*2*SEQL*CONVDIM];   // [b,d,s,c] silu(conv)
__device__ float g_dt   [(size_t)BATCH*2*SEQL*NHEADS];
__device__ float g_dA   [(size_t)BATCH*2*SEQL*NHEADS];
__device__ float g_y    [(size_t)BATCH*2*SEQL*DINNER];    // indexed by ORIGINAL t
__device__ float g_g    [(size_t)ROWS*DINNER];            // combined gated+rmsnormed
__device__ float g_mid  [(size_t)ROWS*DMODEL];
__device__ float g_m    [(size_t)ROWS*DMODEL];
__device__ float g_ff1  [(size_t)ROWS*DFF];
// transposed weights [N, K] K-major (tf32-rounded)
__device__ float g_inwT [(size_t)DPROJ_PAD*DMODEL];
__device__ float g_outwT[(size_t)DMODEL*DINNER];
__device__ float g_ff1T [(size_t)DFF*DMODEL];
__device__ float g_ff2T [(size_t)DMODEL*DFF];

// ---------------- helpers ----------------
__device__ __forceinline__ float siluf(float x){ return x / (1.f + __expf(-x)); }

__device__ __forceinline__ float to_tf32(float x){
    uint32_t u;
    asm("cvt.rna.tf32.f32 %0, %1;" : "=r"(u) : "f"(x));
    return __uint_as_float(u);
}

__device__ __forceinline__ uint32_t smem_u32(const void* p){
    uint32_t a;
    asm("{ .reg .u64 t; cvta.to.shared.u64 t, %1; cvt.u32.u64 %0, t; }" : "=r"(a) : "l"(p));
    return a;
}
__device__ __forceinline__ void cp16(void* smem, const void* g){
    unsigned a = smem_u32(smem);
    asm volatile("cp.async.cg.shared.global [%0], [%1], 16;\n" :: "r"(a), "l"(g));
}
__device__ __forceinline__ void cp4(void* smem, const void* g){
    unsigned a = smem_u32(smem);
    asm volatile("cp.async.ca.shared.global [%0], [%1], 4;\n" :: "r"(a), "l"(g));
}

__device__ __forceinline__ void mma_tf32(float* d, const uint32_t* a, const uint32_t* b){
    asm volatile(
        "mma.sync.aligned.m16n8k8.row.col.f32.tf32.tf32.f32 "
        "{%0,%1,%2,%3}, {%4,%5,%6,%7}, {%8,%9}, {%0,%1,%2,%3};"
        : "+f"(d[0]), "+f"(d[1]), "+f"(d[2]), "+f"(d[3])
        : "r"(a[0]), "r"(a[1]), "r"(a[2]), "r"(a[3]), "r"(b[0]), "r"(b[1]));
}

// ---------------- tiled transpose w/ zero pad + tf32 rounding ----------------
__global__ void transpose_pad_kernel(const float* __restrict__ in, float* __restrict__ out,
                                     int K, int N0, int Npad){
    __shared__ float t[32][33];
    int kb = blockIdx.x*32, nb = blockIdx.y*32;
    int x = threadIdx.x, y = threadIdx.y;   // 32 x 8
    #pragma unroll
    for (int i=0;i<32;i+=8){
        int k = kb + y + i, n = nb + x;
        t[y+i][x] = (n < N0) ? to_tf32(in[(size_t)k*N0 + n]) : 0.f;
    }
    __syncthreads();
    #pragma unroll
    for (int i=0;i<32;i+=8){
        int n = nb + y + i, k = kb + x;
        out[(size_t)n*K + k] = t[x][y+i];
    }
}

// ---------------- layernorm (warp per 512-row), output tf32-rounded ----------------
__global__ void ln_kernel(const float* __restrict__ x, const float* __restrict__ w,
                          const float* __restrict__ b, float* __restrict__ out){
    int row = blockIdx.x*(blockDim.x>>5) + (threadIdx.x>>5);
    int lane = threadIdx.x & 31;
    if (row >= ROWS) return;
    const float* xr = x + (size_t)row*DMODEL;
    float v[16]; float s = 0.f;
    #pragma unroll
    for (int i=0;i<16;i++){ v[i] = xr[lane + 32*i]; s += v[i]; }
    #pragma unroll
    for (int o=16;o;o>>=1) s += __shfl_xor_sync(0xffffffffu, s, o);
    float mu = s * (1.f/DMODEL);
    float s2 = 0.f;
    #pragma unroll
    for (int i=0;i<16;i++){ float d = v[i]-mu; s2 += d*d; }
    #pragma unroll
    for (int o=16;o;o>>=1) s2 += __shfl_xor_sync(0xffffffffu, s2, o);
    float inv = rsqrtf(s2*(1.f/DMODEL) + EPS);
    float* orow = out + (size_t)row*DMODEL;
    #pragma unroll
    for (int i=0;i<16;i++){
        int c = lane + 32*i;
        orow[c] = to_tf32((v[i]-mu)*inv*w[c] + b[c]);
    }
}

// ---------------- tf32 mma.sync GEMM: C[M,N] = A[M,K] @ B[N,K]^T ----------------
// BM=128, BN=128, BK=16, 256 threads (8 warps, 4x2, warp tile 32x64)
// 4-stage cp.async pipeline, one __syncthreads per K-step,
// smem row stride 20 words -> conflict-free LDS (r*20 mod 32 covers all 8 quads)
// EPI: 0 none, 1 bias+gelu(exact) [tf32-rounded out], 2 bias+residual
#define GSTAGES 4
#define GROWSTR 20
#define GSTAGE_F (128*GROWSTR)                       // floats per operand stage
#define GSMEM_BYTES (2*GSTAGES*GSTAGE_F*4)           // 81920

template<int EPI>
__global__ __launch_bounds__(256) void mma_gemm(
    const float* __restrict__ A, const float* __restrict__ Bw, float* __restrict__ C,
    int K, int N, const float* __restrict__ bias, const float* __restrict__ res)
{
    extern __shared__ float sm[];
    float* AsBase = sm;
    float* BsBase = sm + GSTAGES*GSTAGE_F;

    int tid = threadIdx.x, lane = tid & 31, wid = tid >> 5;
    int bm = blockIdx.y * 128, bn = blockIdx.x * 128;
    int wm = (wid >> 1) * 32, wn = (wid & 1) * 64;
    int grp = lane >> 2, tig = lane & 3;

    float acc[2][8][4];
    #pragma unroll
    for (int mi=0;mi<2;mi++)
        #pragma unroll
        for (int ni=0;ni<8;ni++)
            #pragma unroll
            for (int u=0;u<4;u++) acc[mi][ni][u] = 0.f;

    auto load = [&](int st, int k0){
        float* as = AsBase + st*GSTAGE_F;
        float* bs = BsBase + st*GSTAGE_F;
        #pragma unroll
        for (int i=0;i<2;i++){
            int q = tid + i*256;            // 0..511
            int row = q >> 2, c = q & 3;
            cp16(&as[row*GROWSTR + c*4], A + (size_t)(bm+row)*K + k0 + c*4);
        }
        #pragma unroll
        for (int i=0;i<2;i++){
            int q = tid + i*256;
            int row = q >> 2, c = q & 3;
            cp16(&bs[row*GROWSTR + c*4], Bw + (size_t)(bn+row)*K + k0 + c*4);
        }
        asm volatile("cp.async.commit_group;\n");
    };

    int nk = K >> 4;                         // >= 32 for all our GEMMs
    #pragma unroll
    for (int s=0;s<GSTAGES-1;s++) load(s, s << 4);

    for (int kt = 0; kt < nk; kt++){
        asm volatile("cp.async.wait_group %0;\n" :: "n"(GSTAGES-2));
        __syncthreads();
        int nx = kt + GSTAGES - 1;
        if (nx < nk) load(nx % GSTAGES, nx << 4);
        else         asm volatile("cp.async.commit_group;\n");

        const float* as = AsBase + (kt % GSTAGES)*GSTAGE_F;
        const float* bs = BsBase + (kt % GSTAGES)*GSTAGE_F;
        #pragma unroll
        for (int kk = 0; kk < 16; kk += 8){
            uint32_t af[2][4], bf[8][2];
            #pragma unroll
            for (int mi=0;mi<2;mi++){
                int r = wm + mi*16 + grp;
                af[mi][0] = __float_as_uint(as[r*GROWSTR       + kk+tig]);
                af[mi][1] = __float_as_uint(as[(r+8)*GROWSTR   + kk+tig]);
                af[mi][2] = __float_as_uint(as[r*GROWSTR       + kk+tig+4]);
                af[mi][3] = __float_as_uint(as[(r+8)*GROWSTR   + kk+tig+4]);
            }
            #pragma unroll
            for (int ni=0;ni<8;ni++){
                int c0 = wn + ni*8 + grp;
                bf[ni][0] = __float_as_uint(bs[c0*GROWSTR + kk+tig]);
                bf[ni][1] = __float_as_uint(bs[c0*GROWSTR + kk+tig+4]);
            }
            #pragma unroll
            for (int mi=0;mi<2;mi++)
                #pragma unroll
                for (int ni=0;ni<8;ni++)
                    mma_tf32(acc[mi][ni], af[mi], bf[ni]);
        }
    }

    // epilogue: c0,c1 -> row grp, cols tig*2, tig*2+1 ; c2,c3 -> row grp+8
    #pragma unroll
    for (int mi=0;mi<2;mi++){
        #pragma unroll
        for (int half=0; half<2; half++){
            int row = bm + wm + mi*16 + grp + half*8;
            #pragma unroll
            for (int ni=0;ni<8;ni++){
                int col = bn + wn + ni*8 + tig*2;
                float v0 = acc[mi][ni][half*2+0];
                float v1 = acc[mi][ni][half*2+1];
                if (EPI == 1){
                    v0 += bias[col];   v1 += bias[col+1];
                    v0 = 0.5f*v0*(1.f + erff(v0*0.70710678118654752f));
                    v1 = 0.5f*v1*(1.f + erff(v1*0.70710678118654752f));
                    v0 = to_tf32(v0); v1 = to_tf32(v1);
                } else if (EPI == 2){
                    v0 += bias[col]   + res[(size_t)row*N + col];
                    v1 += bias[col+1] + res[(size_t)row*N + col+1];
                }
                float2 v; v.x = v0; v.y = v1;
                *(float2*)(C + (size_t)row*N + col) = v;
            }
        }
    }
}

// ---------------- exact fp32 dt / dA from xn (16 cols of in-proj) ----------------
__global__ void dtda_kernel(const float* __restrict__ in_w,
                            const float* __restrict__ dt_bias,
                            const float* __restrict__ A_log){
    // 256 threads = 16 rows x 16 heads
    int row = blockIdx.x*16 + (threadIdx.x >> 4);
    int h = threadIdx.x & 15;
    const float* xr = g_xn + (size_t)row*DMODEL;
    const float* wc = in_w + 2176 + h;   // column 2176+h, stride DPROJ
    float acc = dt_bias[h];
    #pragma unroll 8
    for (int k = 0; k < DMODEL; k++)
        acc += xr[k] * wc[(size_t)k*DPROJ];
    float dt = (acc > 20.f) ? acc : log1pf(__expf(acc));
    float dA = __expf(-__expf(A_log[h]) * dt);
    int b = row >> 12, t = row & (SEQL-1);
    size_t i0 = ((size_t)(b*2+0)*SEQL + t)*NHEADS + h;
    size_t i1 = ((size_t)(b*2+1)*SEQL + (SEQL-1-t))*NHEADS + h;
    g_dt[i0] = dt; g_dA[i0] = dA;
    g_dt[i1] = dt; g_dA[i1] = dA;
}

// ---------------- depthwise causal conv + silu (per direction) ----------------
__global__ void conv_kernel(const float* __restrict__ cw, const float* __restrict__ cb){
    size_t i = (size_t)blockIdx.x*blockDim.x + threadIdx.x;
    size_t total = (size_t)BATCH*2*SEQL*CONVDIM;
    if (i >= total) return;
    int c = (int)(i % CONVDIM);
    size_t r = i / CONVDIM;
    int s = (int)(r % SEQL);
    int bd = (int)(r / SEQL);
    int d = bd & 1, b = bd >> 1;
    float acc = cb[c];
    #pragma unroll
    for (int k=0;k<DCONV;k++){
        int u = s - (DCONV-1) + k;
        if (u >= 0){
            int t = d ? (SEQL-1-u) : u;
            acc += cw[k*CONVDIM + c] * g_zx[((size_t)(b*SEQL+t))*DPROJ_PAD + DINNER + c];
        }
    }
    g_conv[i] = siluf(acc);
}

// ---------------- selective scan: 64 CTAs (b,d,h), state in registers ----------------
#define CHUNK 16
#define NCHUNK (SEQL/CHUNK)

__global__ __launch_bounds__(256) void scan_kernel(const float* __restrict__ Dh){
    int bx = blockIdx.x;            // 0..63
    int h = bx & 15, d = (bx >> 4) & 1, b = bx >> 5;
    int tid = threadIdx.x;
    int p = tid >> 2, q = tid & 3;  // p: headdim row 0..63, q: state quarter

    __shared__ float buf[2][CHUNK][192];   // [xh 64][B 64][C 64]
    __shared__ float sdt[2][CHUNK], sdA[2][CHUNK];

    const float* base = g_conv + ((size_t)(b*2+d))*SEQL*CONVDIM;
    const float* dtb  = g_dt  + ((size_t)(b*2+d))*SEQL*NHEADS + h;
    const float* dab  = g_dA  + ((size_t)(b*2+d))*SEQL*NHEADS + h;
    float* ybase = g_y + ((size_t)(b*2+d))*SEQL*DINNER;

    float hreg[16];
    #pragma unroll
    for (int i=0;i<16;i++) hreg[i] = 0.f;
    float Dhh = Dh[h];

    auto issue = [&](int c, int sbuf){
        int s0 = c*CHUNK;
        #pragma unroll
        for (int rr=0;rr<3;rr++){
            int j = tid + rr*256;        // 0..767
            int step = j / 48;
            int seg = j % 48;
            int off = seg*4;             // float offset within 192
            const float* src;
            const float* rowp = base + (size_t)(s0+step)*CONVDIM;
            if (off < 64)       src = rowp + h*HEADDIM + off;
            else if (off < 128) src = rowp + DINNER + (off-64);
            else                src = rowp + DINNER + DSTATE + (off-128);
            cp16(&buf[sbuf][step][off], src);
        }
        if (tid < CHUNK)            cp4(&sdt[sbuf][tid],        dtb + (size_t)(s0+tid)*NHEADS);
        else if (tid < 2*CHUNK)     cp4(&sdA[sbuf][tid-CHUNK],  dab + (size_t)(s0+tid-CHUNK)*NHEADS);
        asm volatile("cp.async.commit_group;\n");
    };

    issue(0, 0);
    for (int c=0;c<NCHUNK;c++){
        int cur = c & 1, nxt = cur ^ 1;
        if (c+1 < NCHUNK){
            issue(c+1, nxt);
            asm volatile("cp.async.wait_group 1;\n");
        } else {
            asm volatile("cp.async.wait_group 0;\n");
        }
        __syncthreads();
        #pragma unroll 4
        for (int k=0;k<CHUNK;k++){
            const float* row = buf[cur][k];
            float dt = sdt[cur][k], dA = sdA[cur][k];
            float xh = row[p];
            float dtx = dt*xh;
            const float4* Bp4 = (const float4*)(row + 64 + q*16);
            const float4* Cp4 = (const float4*)(row + 128 + q*16);
            float bv[16], cv[16];
            #pragma unroll
            for (int v2=0; v2<4; v2++){
                float4 bb = Bp4[v2], cc = Cp4[v2];
                bv[4*v2+0]=bb.x; bv[4*v2+1]=bb.y; bv[4*v2+2]=bb.z; bv[4*v2+3]=bb.w;
                cv[4*v2+0]=cc.x; cv[4*v2+1]=cc.y; cv[4*v2+2]=cc.z; cv[4*v2+3]=cc.w;
            }
            float acc = 0.f;
            #pragma unroll
            for (int i=0;i<16;i++){
                hreg[i] = hreg[i]*dA + dtx*bv[i];
                acc += hreg[i]*cv[i];
            }
            acc += __shfl_xor_sync(0xffffffffu, acc, 1);
            acc += __shfl_xor_sync(0xffffffffu, acc, 2);
            if (q == 0){
                int s = c*CHUNK + k;
                int t = d ? (SEQL-1-s) : s;
                ybase[(size_t)t*DINNER + h*HEADDIM + p] = acc + Dhh*xh;
            }
        }
        __syncthreads();
    }
}

// ---------------- gate (silu(z)), per-direction RMS norm, combine (tf32 out) ----------------
__global__ void gate_kernel(const float* __restrict__ mw){
    int row = blockIdx.x;            // 0..8191 (= b*SEQL + t)
    int b = row >> 12, t = row & (SEQL-1);
    const float* z  = g_zx + (size_t)row*DPROJ_PAD;           // cols 0..1024
    const float* y0 = g_y + ((size_t)(b*2+0)*SEQL + t)*DINNER;
    const float* y1 = g_y + ((size_t)(b*2+1)*SEQL + t)*DINNER;
    float g0[4], g1[4];
    float ss0 = 0.f, ss1 = 0.f;
    #pragma unroll
    for (int j=0;j<4;j++){
        int c = threadIdx.x + j*256;
        float zz = z[c];
        float sz = siluf(zz);
        g0[j] = y0[c]*sz; g1[j] = y1[c]*sz;
        ss0 += g0[j]*g0[j]; ss1 += g1[j]*g1[j];
    }
    #pragma unroll
    for (int o=16;o;o>>=1){
        ss0 += __shfl_xor_sync(0xffffffffu, ss0, o);
        ss1 += __shfl_xor_sync(0xffffffffu, ss1, o);
    }
    __shared__ float red[16];
    int wid = threadIdx.x >> 5, lane = threadIdx.x & 31;
    if (lane == 0){ red[wid] = ss0; red[8+wid] = ss1; }
    __syncthreads();
    if (threadIdx.x == 0){
        float a=0.f, bb=0.f;
        #pragma unroll
        for (int w=0;w<8;w++){ a += red[w]; bb += red[8+w]; }
        red[0] = a; red[8] = bb;
    }
    __syncthreads();
    float r0 = rsqrtf(red[0]*(1.f/DINNER) + EPS);
    float r1 = rsqrtf(red[8]*(1.f/DINNER) + EPS);
    float* go = g_g + (size_t)row*DINNER;
    #pragma unroll
    for (int j=0;j<4;j++){
        int c = threadIdx.x + j*256;
        go[c] = to_tf32((g0[j]*r0 + g1[j]*r1) * mw[c]);
    }
}

// ---------------- launch ----------------
extern "C" void kernel_launch(void* const* d_in, const int* in_sizes, int n_in,
                              void* d_out, int out_size)
{
    const float* x        = (const float*)d_in[0];
    const float* nin_w    = (const float*)d_in[1];
    const float* nin_b    = (const float*)d_in[2];
    const float* nout_w   = (const float*)d_in[3];
    const float* nout_b   = (const float*)d_in[4];
    const float* in_w     = (const float*)d_in[5];
    const float* conv_w   = (const float*)d_in[6];
    const float* conv_b   = (const float*)d_in[7];
    const float* dt_bias  = (const float*)d_in[8];
    const float* A_log    = (const float*)d_in[9];
    const float* D_h      = (const float*)d_in[10];
    const float* mnorm_w  = (const float*)d_in[11];
    const float* out_w    = (const float*)d_in[12];
    const float* ff_w1    = (const float*)d_in[13];
    const float* ff_b1    = (const float*)d_in[14];
    const float* ff_w2    = (const float*)d_in[15];
    const float* ff_b2    = (const float*)d_in[16];
    float* out = (float*)d_out;

    float *p_xn, *p_zx, *p_g, *p_mid, *p_m, *p_ff1;
    float *p_inwT, *p_outwT, *p_ff1T, *p_ff2T;
    cudaGetSymbolAddress((void**)&p_xn,   g_xn);
    cudaGetSymbolAddress((void**)&p_zx,   g_zx);
    cudaGetSymbolAddress((void**)&p_g,    g_g);
    cudaGetSymbolAddress((void**)&p_mid,  g_mid);
    cudaGetSymbolAddress((void**)&p_m,    g_m);
    cudaGetSymbolAddress((void**)&p_ff1,  g_ff1);
    cudaGetSymbolAddress((void**)&p_inwT, g_inwT);
    cudaGetSymbolAddress((void**)&p_outwT,g_outwT);
    cudaGetSymbolAddress((void**)&p_ff1T, g_ff1T);
    cudaGetSymbolAddress((void**)&p_ff2T, g_ff2T);

    cudaFuncSetAttribute(mma_gemm<0>, cudaFuncAttributeMaxDynamicSharedMemorySize, GSMEM_BYTES);
    cudaFuncSetAttribute(mma_gemm<1>, cudaFuncAttributeMaxDynamicSharedMemorySize, GSMEM_BYTES);
    cudaFuncSetAttribute(mma_gemm<2>, cudaFuncAttributeMaxDynamicSharedMemorySize, GSMEM_BYTES);

    dim3 tb32(32, 8);
    // weight transposes: out[n*K+k] = tf32(in[k*N0+n])
    transpose_pad_kernel<<<dim3(DMODEL/32, DPROJ_PAD/32), tb32>>>(in_w,  p_inwT,  DMODEL, DPROJ, DPROJ_PAD);
    transpose_pad_kernel<<<dim3(DINNER/32, DMODEL/32),    tb32>>>(out_w, p_outwT, DINNER, DMODEL, DMODEL);
    transpose_pad_kernel<<<dim3(DMODEL/32, DFF/32),       tb32>>>(ff_w1, p_ff1T,  DMODEL, DFF, DFF);
    transpose_pad_kernel<<<dim3(DFF/32, DMODEL/32),       tb32>>>(ff_w2, p_ff2T,  DFF, DMODEL, DMODEL);

    // layernorm in (tf32-rounded output)
    ln_kernel<<<ROWS/8, 256>>>(x, nin_w, nin_b, p_xn);

    // in-proj: xn[8192,512] @ inwT[2304,512]^T -> zx[8192,2304]
    mma_gemm<0><<<dim3(DPROJ_PAD/128, ROWS/128), 256, GSMEM_BYTES>>>(
        p_xn, p_inwT, p_zx, DMODEL, DPROJ_PAD, nullptr, nullptr);

    // exact fp32 dt/dA from xn
    dtda_kernel<<<ROWS/16, 256>>>(in_w, dt_bias, A_log);

    // conv + silu (both directions)
    {
        size_t tot = (size_t)BATCH*2*SEQL*CONVDIM;
        conv_kernel<<<(unsigned)((tot+255)/256), 256>>>(conv_w, conv_b);
    }
    // selective scan
    scan_kernel<<<BATCH*2*NHEADS, 256>>>(D_h);
    // gate + per-dir rmsnorm + combine (tf32 out)
    gate_kernel<<<ROWS, 256>>>(mnorm_w);

    // out-proj: g[8192,1024] @ outwT[512,1024]^T -> mid[8192,512]
    mma_gemm<0><<<dim3(DMODEL/128, ROWS/128), 256, GSMEM_BYTES>>>(
        p_g, p_outwT, p_mid, DINNER, DMODEL, nullptr, nullptr);

    // layernorm out (tf32-rounded output)
    ln_kernel<<<ROWS/8, 256>>>(p_mid, nout_w, nout_b, p_m);

    // FF1 + gelu: m[8192,512] @ ff1T[2048,512]^T -> ff1[8192,2048] (tf32 out)
    mma_gemm<1><<<dim3(DFF/128, ROWS/128), 256, GSMEM_BYTES>>>(
        p_m, p_ff1T, p_ff1, DMODEL, DFF, ff_b1, nullptr);

    // FF2 + bias + residual(x): ff1[8192,2048] @ ff2T[512,2048]^T -> out[8192,512]
    mma_gemm<2><<<dim3(DMODEL/128, ROWS/128), 256, GSMEM_BYTES>>>(
        p_ff1, p_ff2T, out, DFF, DMODEL, ff_b2, x);
}

// round 12
// speedup vs baseline: 1.6178x; 1.0908x over previous
#include <cuda_runtime.h>
#include <cuda_fp16.h>
#include <math.h>
#include <stdint.h>

// ---------------- problem constants ----------------
#define BATCH 2
#define SEQL 4096
#define DMODEL 512
#define DSTATE 64
#define DCONV 4
#define HEADDIM 64
#define DINNER 1024
#define NHEADS 16
#define CONVDIM 1152          // DINNER + 2*DSTATE
#define DPROJ 2192            // 2*DINNER + 2*DSTATE + NHEADS
#define DPROJ_PAD 2304        // padded to multiple of 128
#define ROWS (BATCH*SEQL)     // 8192
#define DFF 2048
#define EPS 1e-5f

// ---------------- scratch (static device mem; no allocations) ----------------
__device__ __half g_xn   [(size_t)ROWS*DMODEL];           // fp16 LN output (GEMM A + dtda)
__device__ float  g_zx   [(size_t)ROWS*DPROJ_PAD];
__device__ float  g_conv [(size_t)BATCH*2*SEQL*CONVDIM];  // [b,d,s,c] silu(conv)
__device__ float  g_dt   [(size_t)BATCH*2*SEQL*NHEADS];
__device__ float  g_dA   [(size_t)BATCH*2*SEQL*NHEADS];
__device__ float  g_y    [(size_t)BATCH*2*SEQL*DINNER];   // indexed by ORIGINAL t
__device__ __half g_g    [(size_t)ROWS*DINNER];           // gated+rmsnormed (GEMM A)
__device__ float  g_mid  [(size_t)ROWS*DMODEL];
__device__ __half g_m    [(size_t)ROWS*DMODEL];           // LN output (GEMM A)
__device__ __half g_ff1  [(size_t)ROWS*DFF];              // gelu output (GEMM A)
// transposed weights [N, K] K-major, fp16
__device__ __half g_inwT [(size_t)DPROJ_PAD*DMODEL];
__device__ __half g_outwT[(size_t)DMODEL*DINNER];
__device__ __half g_ff1T [(size_t)DFF*DMODEL];
__device__ __half g_ff2T [(size_t)DMODEL*DFF];

// ---------------- helpers ----------------
__device__ __forceinline__ float siluf(float x){ return x / (1.f + __expf(-x)); }

__device__ __forceinline__ uint32_t smem_u32(const void* p){
    uint32_t a;
    asm("{ .reg .u64 t; cvta.to.shared.u64 t, %1; cvt.u32.u64 %0, t; }" : "=r"(a) : "l"(p));
    return a;
}
__device__ __forceinline__ void cp16(void* smem, const void* g){
    unsigned a = smem_u32(smem);
    asm volatile("cp.async.cg.shared.global [%0], [%1], 16;\n" :: "r"(a), "l"(g));
}
__device__ __forceinline__ void cp4(void* smem, const void* g){
    unsigned a = smem_u32(smem);
    asm volatile("cp.async.ca.shared.global [%0], [%1], 4;\n" :: "r"(a), "l"(g));
}

__device__ __forceinline__ void mma_f16(float* d, const uint32_t* a, const uint32_t* b){
    asm volatile(
        "mma.sync.aligned.m16n8k16.row.col.f32.f16.f16.f32 "
        "{%0,%1,%2,%3}, {%4,%5,%6,%7}, {%8,%9}, {%0,%1,%2,%3};"
        : "+f"(d[0]), "+f"(d[1]), "+f"(d[2]), "+f"(d[3])
        : "r"(a[0]), "r"(a[1]), "r"(a[2]), "r"(a[3]), "r"(b[0]), "r"(b[1]));
}

// ---------------- tiled transpose w/ zero pad -> fp16: out[n*K+k] = h(in[k*N0+n]) ----------------
__global__ void transpose_pad_kernel(const float* __restrict__ in, __half* __restrict__ out,
                                     int K, int N0, int Npad){
    __shared__ float t[32][33];
    int kb = blockIdx.x*32, nb = blockIdx.y*32;
    int x = threadIdx.x, y = threadIdx.y;   // 32 x 8
    #pragma unroll
    for (int i=0;i<32;i+=8){
        int k = kb + y + i, n = nb + x;
        t[y+i][x] = (n < N0) ? in[(size_t)k*N0 + n] : 0.f;
    }
    __syncthreads();
    #pragma unroll
    for (int i=0;i<32;i+=8){
        int n = nb + y + i, k = kb + x;
        out[(size_t)n*K + k] = __float2half_rn(t[x][y+i]);
    }
}

// ---------------- layernorm (warp per 512-row), fp16 output ----------------
__global__ void ln_kernel(const float* __restrict__ x, const float* __restrict__ w,
                          const float* __restrict__ b, __half* __restrict__ out){
    int row = blockIdx.x*(blockDim.x>>5) + (threadIdx.x>>5);
    int lane = threadIdx.x & 31;
    if (row >= ROWS) return;
    const float* xr = x + (size_t)row*DMODEL;
    float v[16]; float s = 0.f;
    #pragma unroll
    for (int i=0;i<16;i++){ v[i] = xr[lane + 32*i]; s += v[i]; }
    #pragma unroll
    for (int o=16;o;o>>=1) s += __shfl_xor_sync(0xffffffffu, s, o);
    float mu = s * (1.f/DMODEL);
    float s2 = 0.f;
    #pragma unroll
    for (int i=0;i<16;i++){ float d = v[i]-mu; s2 += d*d; }
    #pragma unroll
    for (int o=16;o;o>>=1) s2 += __shfl_xor_sync(0xffffffffu, s2, o);
    float inv = rsqrtf(s2*(1.f/DMODEL) + EPS);
    __half* orow = out + (size_t)row*DMODEL;
    #pragma unroll
    for (int i=0;i<16;i++){
        int c = lane + 32*i;
        orow[c] = __float2half_rn((v[i]-mu)*inv*w[c] + b[c]);
    }
}

// ---------------- fp16 mma.sync GEMM: C[M,N] = A[M,K] @ B[N,K]^T (fp32 accum) ----------------
// BM=128, BN=128, BK=16, 256 threads (8 warps 4x2, warp tile 32x64)
// 4-stage cp.async pipeline, static 48KB smem, stride-24-half rows (conflict-free LDS)
// EPI: 0 none (float out), 1 bias+gelu(exact) -> HALF out, 2 bias+residual (float out)
#define GSTAGES 4
#define HROWSTR 24
#define HSTAGE_H (128*HROWSTR)

template<int EPI>
__global__ __launch_bounds__(256) void mma_gemm(
    const __half* __restrict__ A, const __half* __restrict__ Bw,
    float* __restrict__ C, __half* __restrict__ Ch,
    int K, int N, const float* __restrict__ bias, const float* __restrict__ res)
{
    __shared__ __half sA[GSTAGES][HSTAGE_H];
    __shared__ __half sB[GSTAGES][HSTAGE_H];

    int tid = threadIdx.x, lane = tid & 31, wid = tid >> 5;
    int bm = blockIdx.y * 128, bn = blockIdx.x * 128;
    int wm = (wid >> 1) * 32, wn = (wid & 1) * 64;
    int grp = lane >> 2, tig = lane & 3;

    float acc[2][8][4];
    #pragma unroll
    for (int mi=0;mi<2;mi++)
        #pragma unroll
        for (int ni=0;ni<8;ni++)
            #pragma unroll
            for (int u=0;u<4;u++) acc[mi][ni][u] = 0.f;

    int lrow = tid >> 1, lc = tid & 1;     // 128 rows x 2 16B-chunks
    auto load = [&](int st, int k0){
        cp16(&sA[st][lrow*HROWSTR + lc*8], A + (size_t)(bm+lrow)*K + k0 + lc*8);
        cp16(&sB[st][lrow*HROWSTR + lc*8], Bw + (size_t)(bn+lrow)*K + k0 + lc*8);
        asm volatile("cp.async.commit_group;\n");
    };

    int nk = K >> 4;                       // >= 32 for all our GEMMs
    #pragma unroll
    for (int s=0;s<GSTAGES-1;s++) load(s, s << 4);

    for (int kt = 0; kt < nk; kt++){
        asm volatile("cp.async.wait_group %0;\n" :: "n"(GSTAGES-2));
        __syncthreads();
        int nx = kt + GSTAGES - 1;
        if (nx < nk) load(nx % GSTAGES, nx << 4);
        else         asm volatile("cp.async.commit_group;\n");

        const __half* as = sA[kt % GSTAGES];
        const __half* bs = sB[kt % GSTAGES];
        uint32_t af[2][4], bf[8][2];
        #pragma unroll
        for (int mi=0;mi<2;mi++){
            int r = wm + mi*16 + grp;
            af[mi][0] = *(const uint32_t*)&as[r*HROWSTR     + tig*2];
            af[mi][1] = *(const uint32_t*)&as[(r+8)*HROWSTR + tig*2];
            af[mi][2] = *(const uint32_t*)&as[r*HROWSTR     + tig*2 + 8];
            af[mi][3] = *(const uint32_t*)&as[(r+8)*HROWSTR + tig*2 + 8];
        }
        #pragma unroll
        for (int ni=0;ni<8;ni++){
            int c0 = wn + ni*8 + grp;
            bf[ni][0] = *(const uint32_t*)&bs[c0*HROWSTR + tig*2];
            bf[ni][1] = *(const uint32_t*)&bs[c0*HROWSTR + tig*2 + 8];
        }
        #pragma unroll
        for (int mi=0;mi<2;mi++)
            #pragma unroll
            for (int ni=0;ni<8;ni++)
                mma_f16(acc[mi][ni], af[mi], bf[ni]);
        __syncthreads();
    }

    // epilogue: c0,c1 -> row grp, cols tig*2,+1 ; c2,c3 -> row grp+8
    #pragma unroll
    for (int mi=0;mi<2;mi++){
        #pragma unroll
        for (int half2_=0; half2_<2; half2_++){
            int row = bm + wm + mi*16 + grp + half2_*8;
            #pragma unroll
            for (int ni=0;ni<8;ni++){
                int col = bn + wn + ni*8 + tig*2;
                float v0 = acc[mi][ni][half2_*2+0];
                float v1 = acc[mi][ni][half2_*2+1];
                if (EPI == 1){
                    v0 += bias[col];   v1 += bias[col+1];
                    v0 = 0.5f*v0*(1.f + erff(v0*0.70710678118654752f));
                    v1 = 0.5f*v1*(1.f + erff(v1*0.70710678118654752f));
                    __half2 hv; hv.x = __float2half_rn(v0); hv.y = __float2half_rn(v1);
                    *(__half2*)(Ch + (size_t)row*N + col) = hv;
                } else {
                    if (EPI == 2){
                        v0 += bias[col]   + res[(size_t)row*N + col];
                        v1 += bias[col+1] + res[(size_t)row*N + col+1];
                    }
                    float2 v; v.x = v0; v.y = v1;
                    *(float2*)(C + (size_t)row*N + col) = v;
                }
            }
        }
    }
}

// ---------------- dt / dA from fp16 xn (exact fp32 dot, fp32 weights) ----------------
__global__ void dtda_kernel(const float* __restrict__ in_w,
                            const float* __restrict__ dt_bias,
                            const float* __restrict__ A_log){
    // 256 threads = 16 rows x 16 heads
    int row = blockIdx.x*16 + (threadIdx.x >> 4);
    int h = threadIdx.x & 15;
    const __half* xr = g_xn + (size_t)row*DMODEL;
    const float* wc = in_w + 2176 + h;   // column 2176+h, stride DPROJ
    float acc = dt_bias[h];
    #pragma unroll 8
    for (int k = 0; k < DMODEL; k++)
        acc += __half2float(xr[k]) * wc[(size_t)k*DPROJ];
    float dt = (acc > 20.f) ? acc : log1pf(__expf(acc));
    float dA = __expf(-__expf(A_log[h]) * dt);
    int b = row >> 12, t = row & (SEQL-1);
    size_t i0 = ((size_t)(b*2+0)*SEQL + t)*NHEADS + h;
    size_t i1 = ((size_t)(b*2+1)*SEQL + (SEQL-1-t))*NHEADS + h;
    g_dt[i0] = dt; g_dA[i0] = dA;
    g_dt[i1] = dt; g_dA[i1] = dA;
}

// ---------------- depthwise causal conv + silu (per direction) ----------------
__global__ void conv_kernel(const float* __restrict__ cw, const float* __restrict__ cb){
    size_t i = (size_t)blockIdx.x*blockDim.x + threadIdx.x;
    size_t total = (size_t)BATCH*2*SEQL*CONVDIM;
    if (i >= total) return;
    int c = (int)(i % CONVDIM);
    size_t r = i / CONVDIM;
    int s = (int)(r % SEQL);
    int bd = (int)(r / SEQL);
    int d = bd & 1, b = bd >> 1;
    float acc = cb[c];
    #pragma unroll
    for (int k=0;k<DCONV;k++){
        int u = s - (DCONV-1) + k;
        if (u >= 0){
            int t = d ? (SEQL-1-u) : u;
            acc += cw[k*CONVDIM + c] * g_zx[((size_t)(b*SEQL+t))*DPROJ_PAD + DINNER + c];
        }
    }
    g_conv[i] = siluf(acc);
}

// ---------------- selective scan: 64 CTAs (b,d,h), state in registers ----------------
#define CHUNK 16
#define NCHUNK (SEQL/CHUNK)

__global__ __launch_bounds__(256) void scan_kernel(const float* __restrict__ Dh){
    int bx = blockIdx.x;            // 0..63
    int h = bx & 15, d = (bx >> 4) & 1, b = bx >> 5;
    int tid = threadIdx.x;
    int p = tid >> 2, q = tid & 3;  // p: headdim row 0..63, q: state quarter

    __shared__ float buf[2][CHUNK][192];   // [xh 64][B 64][C 64]
    __shared__ float sdt[2][CHUNK], sdA[2][CHUNK];

    const float* base = g_conv + ((size_t)(b*2+d))*SEQL*CONVDIM;
    const float* dtb  = g_dt  + ((size_t)(b*2+d))*SEQL*NHEADS + h;
    const float* dab  = g_dA  + ((size_t)(b*2+d))*SEQL*NHEADS + h;
    float* ybase = g_y + ((size_t)(b*2+d))*SEQL*DINNER;

    float hreg[16];
    #pragma unroll
    for (int i=0;i<16;i++) hreg[i] = 0.f;
    float Dhh = Dh[h];

    auto issue = [&](int c, int sbuf){
        int s0 = c*CHUNK;
        #pragma unroll
        for (int rr=0;rr<3;rr++){
            int j = tid + rr*256;        // 0..767
            int step = j / 48;
            int seg = j % 48;
            int off = seg*4;             // float offset within 192
            const float* src;
            const float* rowp = base + (size_t)(s0+step)*CONVDIM;
            if (off < 64)       src = rowp + h*HEADDIM + off;
            else if (off < 128) src = rowp + DINNER + (off-64);
            else                src = rowp + DINNER + DSTATE + (off-128);
            cp16(&buf[sbuf][step][off], src);
        }
        if (tid < CHUNK)            cp4(&sdt[sbuf][tid],        dtb + (size_t)(s0+tid)*NHEADS);
        else if (tid < 2*CHUNK)     cp4(&sdA[sbuf][tid-CHUNK],  dab + (size_t)(s0+tid-CHUNK)*NHEADS);
        asm volatile("cp.async.commit_group;\n");
    };

    issue(0, 0);
    for (int c=0;c<NCHUNK;c++){
        int cur = c & 1, nxt = cur ^ 1;
        if (c+1 < NCHUNK){
            issue(c+1, nxt);
            asm volatile("cp.async.wait_group 1;\n");
        } else {
            asm volatile("cp.async.wait_group 0;\n");
        }
        __syncthreads();
        #pragma unroll 4
        for (int k=0;k<CHUNK;k++){
            const float* row = buf[cur][k];
            float dt = sdt[cur][k], dA = sdA[cur][k];
            float xh = row[p];
            float dtx = dt*xh;
            const float4* Bp4 = (const float4*)(row + 64 + q*16);
            const float4* Cp4 = (const float4*)(row + 128 + q*16);
            float bv[16], cv[16];
            #pragma unroll
            for (int v2=0; v2<4; v2++){
                float4 bb = Bp4[v2], cc = Cp4[v2];
                bv[4*v2+0]=bb.x; bv[4*v2+1]=bb.y; bv[4*v2+2]=bb.z; bv[4*v2+3]=bb.w;
                cv[4*v2+0]=cc.x; cv[4*v2+1]=cc.y; cv[4*v2+2]=cc.z; cv[4*v2+3]=cc.w;
            }
            float acc = 0.f;
            #pragma unroll
            for (int i=0;i<16;i++){
                hreg[i] = hreg[i]*dA + dtx*bv[i];
                acc += hreg[i]*cv[i];
            }
            acc += __shfl_xor_sync(0xffffffffu, acc, 1);
            acc += __shfl_xor_sync(0xffffffffu, acc, 2);
            if (q == 0){
                int s = c*CHUNK + k;
                int t = d ? (SEQL-1-s) : s;
                ybase[(size_t)t*DINNER + h*HEADDIM + p] = acc + Dhh*xh;
            }
        }
        __syncthreads();
    }
}

// ---------------- gate (silu(z)), per-direction RMS norm, combine -> fp16 ----------------
__global__ void gate_kernel(const float* __restrict__ mw){
    int row = blockIdx.x;            // 0..8191 (= b*SEQL + t)
    int b = row >> 12, t = row & (SEQL-1);
    const float* z  = g_zx + (size_t)row*DPROJ_PAD;           // cols 0..1024
    const float* y0 = g_y + ((size_t)(b*2+0)*SEQL + t)*DINNER;
    const float* y1 = g_y + ((size_t)(b*2+1)*SEQL + t)*DINNER;
    float g0[4], g1[4];
    float ss0 = 0.f, ss1 = 0.f;
    #pragma unroll
    for (int j=0;j<4;j++){
        int c = threadIdx.x + j*256;
        float zz = z[c];
        float sz = siluf(zz);
        g0[j] = y0[c]*sz; g1[j] = y1[c]*sz;
        ss0 += g0[j]*g0[j]; ss1 += g1[j]*g1[j];
    }
    #pragma unroll
    for (int o=16;o;o>>=1){
        ss0 += __shfl_xor_sync(0xffffffffu, ss0, o);
        ss1 += __shfl_xor_sync(0xffffffffu, ss1, o);
    }
    __shared__ float red[16];
    int wid = threadIdx.x >> 5, lane = threadIdx.x & 31;
    if (lane == 0){ red[wid] = ss0; red[8+wid] = ss1; }
    __syncthreads();
    if (threadIdx.x == 0){
        float a=0.f, bb=0.f;
        #pragma unroll
        for (int w=0;w<8;w++){ a += red[w]; bb += red[8+w]; }
        red[0] = a; red[8] = bb;
    }
    __syncthreads();
    float r0 = rsqrtf(red[0]*(1.f/DINNER) + EPS);
    float r1 = rsqrtf(red[8]*(1.f/DINNER) + EPS);
    __half* go = g_g + (size_t)row*DINNER;
    #pragma unroll
    for (int j=0;j<4;j++){
        int c = threadIdx.x + j*256;
        go[c] = __float2half_rn((g0[j]*r0 + g1[j]*r1) * mw[c]);
    }
}

// ---------------- launch ----------------
extern "C" void kernel_launch(void* const* d_in, const int* in_sizes, int n_in,
                              void* d_out, int out_size)
{
    const float* x        = (const float*)d_in[0];
    const float* nin_w    = (const float*)d_in[1];
    const float* nin_b    = (const float*)d_in[2];
    const float* nout_w   = (const float*)d_in[3];
    const float* nout_b   = (const float*)d_in[4];
    const float* in_w     = (const float*)d_in[5];
    const float* conv_w   = (const float*)d_in[6];
    const float* conv_b   = (const float*)d_in[7];
    const float* dt_bias  = (const float*)d_in[8];
    const float* A_log    = (const float*)d_in[9];
    const float* D_h      = (const float*)d_in[10];
    const float* mnorm_w  = (const float*)d_in[11];
    const float* out_w    = (const float*)d_in[12];
    const float* ff_w1    = (const float*)d_in[13];
    const float* ff_b1    = (const float*)d_in[14];
    const float* ff_w2    = (const float*)d_in[15];
    const float* ff_b2    = (const float*)d_in[16];
    float* out = (float*)d_out;

    float *p_zx, *p_mid;
    __half *p_xn, *p_g, *p_m, *p_ff1;
    __half *p_inwT, *p_outwT, *p_ff1T, *p_ff2T;
    cudaGetSymbolAddress((void**)&p_xn,   g_xn);
    cudaGetSymbolAddress((void**)&p_zx,   g_zx);
    cudaGetSymbolAddress((void**)&p_g,    g_g);
    cudaGetSymbolAddress((void**)&p_mid,  g_mid);
    cudaGetSymbolAddress((void**)&p_m,    g_m);
    cudaGetSymbolAddress((void**)&p_ff1,  g_ff1);
    cudaGetSymbolAddress((void**)&p_inwT, g_inwT);
    cudaGetSymbolAddress((void**)&p_outwT,g_outwT);
    cudaGetSymbolAddress((void**)&p_ff1T, g_ff1T);
    cudaGetSymbolAddress((void**)&p_ff2T, g_ff2T);

    dim3 tb32(32, 8);
    // weight transposes: out[n*K+k] = h(in[k*N0+n])
    transpose_pad_kernel<<<dim3(DMODEL/32, DPROJ_PAD/32), tb32>>>(in_w,  p_inwT,  DMODEL, DPROJ, DPROJ_PAD);
    transpose_pad_kernel<<<dim3(DINNER/32, DMODEL/32),    tb32>>>(out_w, p_outwT, DINNER, DMODEL, DMODEL);
    transpose_pad_kernel<<<dim3(DMODEL/32, DFF/32),       tb32>>>(ff_w1, p_ff1T,  DMODEL, DFF, DFF);
    transpose_pad_kernel<<<dim3(DFF/32, DMODEL/32),       tb32>>>(ff_w2, p_ff2T,  DFF, DMODEL, DMODEL);

    // layernorm in (fp16 output)
    ln_kernel<<<ROWS/8, 256>>>(x, nin_w, nin_b, p_xn);

    // in-proj: xn[8192,512] @ inwT[2304,512]^T -> zx[8192,2304] (fp32)
    mma_gemm<0><<<dim3(DPROJ_PAD/128, ROWS/128), 256>>>(
        p_xn, p_inwT, p_zx, nullptr, DMODEL, DPROJ_PAD, nullptr, nullptr);

    // dt/dA from fp16 xn (fp32 dot with fp32 weights)
    dtda_kernel<<<ROWS/16, 256>>>(in_w, dt_bias, A_log);

    // conv + silu (both directions)
    {
        size_t tot = (size_t)BATCH*2*SEQL*CONVDIM;
        conv_kernel<<<(unsigned)((tot+255)/256), 256>>>(conv_w, conv_b);
    }
    // selective scan
    scan_kernel<<<BATCH*2*NHEADS, 256>>>(D_h);
    // gate + per-dir rmsnorm + combine (fp16 out)
    gate_kernel<<<ROWS, 256>>>(mnorm_w);

    // out-proj: g[8192,1024] @ outwT[512,1024]^T -> mid[8192,512] (fp32)
    mma_gemm<0><<<dim3(DMODEL/128, ROWS/128), 256>>>(
        p_g, p_outwT, p_mid, nullptr, DINNER, DMODEL, nullptr, nullptr);

    // layernorm out (fp16 output)
    ln_kernel<<<ROWS/8, 256>>>(p_mid, nout_w, nout_b, p_m);

    // FF1 + gelu: m[8192,512] @ ff1T[2048,512]^T -> ff1[8192,2048] (fp16 out)
    mma_gemm<1><<<dim3(DFF/128, ROWS/128), 256>>>(
        p_m, p_ff1T, nullptr, p_ff1, DMODEL, DFF, ff_b1, nullptr);

    // FF2 + bias + residual(x): ff1[8192,2048] @ ff2T[512,2048]^T -> out[8192,512] (fp32)
    mma_gemm<2><<<dim3(DMODEL/128, ROWS/128), 256>>>(
        p_ff1, p_ff2T, out, nullptr, DFF, DMODEL, ff_b2, x);
}

// round 13
// speedup vs baseline: 1.6401x; 1.0137x over previous
#include <cuda_runtime.h>
#include <cuda_fp16.h>
#include <math.h>
#include <stdint.h>

// ---------------- problem constants ----------------
#define BATCH 2
#define SEQL 4096
#define DMODEL 512
#define DSTATE 64
#define DCONV 4
#define HEADDIM 64
#define DINNER 1024
#define NHEADS 16
#define CONVDIM 1152          // DINNER + 2*DSTATE
#define DPROJ 2192            // 2*DINNER + 2*DSTATE + NHEADS
#define DPROJ_PAD 2304        // padded to multiple of 128
#define ROWS (BATCH*SEQL)     // 8192
#define DFF 2048
#define EPS 1e-5f

// ---------------- scratch (static device mem; no allocations) ----------------
__device__ __half g_xn   [(size_t)ROWS*DMODEL];           // fp16 LN output (GEMM A + dtda)
__device__ float  g_zx   [(size_t)ROWS*DPROJ_PAD];
__device__ float  g_conv [(size_t)BATCH*2*SEQL*CONVDIM];  // [b,d,s,c] silu(conv)
__device__ float  g_dt   [(size_t)BATCH*2*SEQL*NHEADS];
__device__ float  g_dA   [(size_t)BATCH*2*SEQL*NHEADS];
__device__ float  g_y    [(size_t)BATCH*2*SEQL*DINNER];   // indexed by ORIGINAL t
__device__ __half g_g    [(size_t)ROWS*DINNER];           // gated+rmsnormed (GEMM A)
__device__ float  g_mid  [(size_t)ROWS*DMODEL];
__device__ __half g_m    [(size_t)ROWS*DMODEL];           // LN output (GEMM A)
__device__ __half g_ff1  [(size_t)ROWS*DFF];              // gelu output (GEMM A)
// transposed weights [N, K] K-major, fp16
__device__ __half g_inwT [(size_t)DPROJ_PAD*DMODEL];
__device__ __half g_outwT[(size_t)DMODEL*DINNER];
__device__ __half g_ff1T [(size_t)DFF*DMODEL];
__device__ __half g_ff2T [(size_t)DMODEL*DFF];

// ---------------- helpers ----------------
// silu via single-MUFU tanh: x*sigmoid(x) = 0.5x*(1+tanh(x/2))
__device__ __forceinline__ float siluf(float x){
    float t;
    asm("tanh.approx.f32 %0, %1;" : "=f"(t) : "f"(0.5f*x));
    return 0.5f*x*(1.f + t);
}

__device__ __forceinline__ uint32_t smem_u32(const void* p){
    uint32_t a;
    asm("{ .reg .u64 t; cvta.to.shared.u64 t, %1; cvt.u32.u64 %0, t; }" : "=r"(a) : "l"(p));
    return a;
}
__device__ __forceinline__ void cp16(void* smem, const void* g){
    unsigned a = smem_u32(smem);
    asm volatile("cp.async.cg.shared.global [%0], [%1], 16;\n" :: "r"(a), "l"(g));
}
__device__ __forceinline__ void cp4(void* smem, const void* g){
    unsigned a = smem_u32(smem);
    asm volatile("cp.async.ca.shared.global [%0], [%1], 4;\n" :: "r"(a), "l"(g));
}

__device__ __forceinline__ void mma_f16(float* d, const uint32_t* a, const uint32_t* b){
    asm volatile(
        "mma.sync.aligned.m16n8k16.row.col.f32.f16.f16.f32 "
        "{%0,%1,%2,%3}, {%4,%5,%6,%7}, {%8,%9}, {%0,%1,%2,%3};"
        : "+f"(d[0]), "+f"(d[1]), "+f"(d[2]), "+f"(d[3])
        : "r"(a[0]), "r"(a[1]), "r"(a[2]), "r"(a[3]), "r"(b[0]), "r"(b[1]));
}

// ---------------- batched transpose of all 4 weights -> fp16 [N,K] K-major ----------------
// tile table: [0,1152) in_w ; [1152,1664) out_w ; [1664,2688) ff_w1 ; [2688,3712) ff_w2
__global__ void transpose_all_kernel(const float* __restrict__ in_w,  __half* __restrict__ o_inw,
                                     const float* __restrict__ out_w, __half* __restrict__ o_outw,
                                     const float* __restrict__ ff_w1, __half* __restrict__ o_ff1,
                                     const float* __restrict__ ff_w2, __half* __restrict__ o_ff2){
    int tile = blockIdx.x;
    const float* in; __half* out; int K, N0, ktiles;
    if (tile < 1152){            in = in_w;  out = o_inw;  K = DMODEL; N0 = DPROJ; ktiles = 16; }
    else if (tile < 1664){ tile -= 1152; in = out_w; out = o_outw; K = DINNER; N0 = DMODEL; ktiles = 32; }
    else if (tile < 2688){ tile -= 1664; in = ff_w1; out = o_ff1;  K = DMODEL; N0 = DFF;    ktiles = 16; }
    else {                 tile -= 2688; in = ff_w2; out = o_ff2;  K = DFF;    N0 = DMODEL; ktiles = 64; }
    int kb = (tile % ktiles)*32, nb = (tile / ktiles)*32;

    __shared__ float t[32][33];
    int x = threadIdx.x, y = threadIdx.y;   // 32 x 8
    #pragma unroll
    for (int i=0;i<32;i+=8){
        int k = kb + y + i, n = nb + x;
        t[y+i][x] = (n < N0) ? in[(size_t)k*N0 + n] : 0.f;
    }
    __syncthreads();
    #pragma unroll
    for (int i=0;i<32;i+=8){
        int n = nb + y + i, k = kb + x;
        out[(size_t)n*K + k] = __float2half_rn(t[x][y+i]);
    }
}

// ---------------- layernorm (warp per 512-row), fp16 output ----------------
__global__ void ln_kernel(const float* __restrict__ x, const float* __restrict__ w,
                          const float* __restrict__ b, __half* __restrict__ out){
    int row = blockIdx.x*(blockDim.x>>5) + (threadIdx.x>>5);
    int lane = threadIdx.x & 31;
    if (row >= ROWS) return;
    const float* xr = x + (size_t)row*DMODEL;
    float v[16]; float s = 0.f;
    #pragma unroll
    for (int i=0;i<16;i++){ v[i] = xr[lane + 32*i]; s += v[i]; }
    #pragma unroll
    for (int o=16;o;o>>=1) s += __shfl_xor_sync(0xffffffffu, s, o);
    float mu = s * (1.f/DMODEL);
    float s2 = 0.f;
    #pragma unroll
    for (int i=0;i<16;i++){ float d = v[i]-mu; s2 += d*d; }
    #pragma unroll
    for (int o=16;o;o>>=1) s2 += __shfl_xor_sync(0xffffffffu, s2, o);
    float inv = rsqrtf(s2*(1.f/DMODEL) + EPS);
    __half* orow = out + (size_t)row*DMODEL;
    #pragma unroll
    for (int i=0;i<16;i++){
        int c = lane + 32*i;
        orow[c] = __float2half_rn((v[i]-mu)*inv*w[c] + b[c]);
    }
}

// ---------------- fp16 mma.sync GEMM: C[M,N] = A[M,K] @ B[N,K]^T (fp32 accum) ----------------
// BM=128, BN=128, BK=16, 256 threads (8 warps 4x2, warp tile 32x64)
// 4-stage cp.async pipeline, static 48KB smem, stride-24-half rows (conflict-free LDS)
// EPI: 0 none (float out), 1 bias+gelu(exact) -> HALF out, 2 bias+residual (float out)
#define GSTAGES 4
#define HROWSTR 24
#define HSTAGE_H (128*HROWSTR)

template<int EPI>
__global__ __launch_bounds__(256) void mma_gemm(
    const __half* __restrict__ A, const __half* __restrict__ Bw,
    float* __restrict__ C, __half* __restrict__ Ch,
    int K, int N, const float* __restrict__ bias, const float* __restrict__ res)
{
    __shared__ __half sA[GSTAGES][HSTAGE_H];
    __shared__ __half sB[GSTAGES][HSTAGE_H];

    int tid = threadIdx.x, lane = tid & 31, wid = tid >> 5;
    int bm = blockIdx.y * 128, bn = blockIdx.x * 128;
    int wm = (wid >> 1) * 32, wn = (wid & 1) * 64;
    int grp = lane >> 2, tig = lane & 3;

    float acc[2][8][4];
    #pragma unroll
    for (int mi=0;mi<2;mi++)
        #pragma unroll
        for (int ni=0;ni<8;ni++)
            #pragma unroll
            for (int u=0;u<4;u++) acc[mi][ni][u] = 0.f;

    int lrow = tid >> 1, lc = tid & 1;     // 128 rows x 2 16B-chunks
    auto load = [&](int st, int k0){
        cp16(&sA[st][lrow*HROWSTR + lc*8], A + (size_t)(bm+lrow)*K + k0 + lc*8);
        cp16(&sB[st][lrow*HROWSTR + lc*8], Bw + (size_t)(bn+lrow)*K + k0 + lc*8);
        asm volatile("cp.async.commit_group;\n");
    };

    int nk = K >> 4;                       // >= 32 for all our GEMMs
    #pragma unroll
    for (int s=0;s<GSTAGES-1;s++) load(s, s << 4);

    for (int kt = 0; kt < nk; kt++){
        asm volatile("cp.async.wait_group %0;\n" :: "n"(GSTAGES-2));
        __syncthreads();
        int nx = kt + GSTAGES - 1;
        if (nx < nk) load(nx % GSTAGES, nx << 4);
        else         asm volatile("cp.async.commit_group;\n");

        const __half* as = sA[kt % GSTAGES];
        const __half* bs = sB[kt % GSTAGES];
        uint32_t af[2][4], bf[8][2];
        #pragma unroll
        for (int mi=0;mi<2;mi++){
            int r = wm + mi*16 + grp;
            af[mi][0] = *(const uint32_t*)&as[r*HROWSTR     + tig*2];
            af[mi][1] = *(const uint32_t*)&as[(r+8)*HROWSTR + tig*2];
            af[mi][2] = *(const uint32_t*)&as[r*HROWSTR     + tig*2 + 8];
            af[mi][3] = *(const uint32_t*)&as[(r+8)*HROWSTR + tig*2 + 8];
        }
        #pragma unroll
        for (int ni=0;ni<8;ni++){
            int c0 = wn + ni*8 + grp;
            bf[ni][0] = *(const uint32_t*)&bs[c0*HROWSTR + tig*2];
            bf[ni][1] = *(const uint32_t*)&bs[c0*HROWSTR + tig*2 + 8];
        }
        #pragma unroll
        for (int mi=0;mi<2;mi++)
            #pragma unroll
            for (int ni=0;ni<8;ni++)
                mma_f16(acc[mi][ni], af[mi], bf[ni]);
        __syncthreads();
    }

    // epilogue: c0,c1 -> row grp, cols tig*2,+1 ; c2,c3 -> row grp+8
    #pragma unroll
    for (int mi=0;mi<2;mi++){
        #pragma unroll
        for (int half2_=0; half2_<2; half2_++){
            int row = bm + wm + mi*16 + grp + half2_*8;
            #pragma unroll
            for (int ni=0;ni<8;ni++){
                int col = bn + wn + ni*8 + tig*2;
                float v0 = acc[mi][ni][half2_*2+0];
                float v1 = acc[mi][ni][half2_*2+1];
                if (EPI == 1){
                    v0 += bias[col];   v1 += bias[col+1];
                    v0 = 0.5f*v0*(1.f + erff(v0*0.70710678118654752f));
                    v1 = 0.5f*v1*(1.f + erff(v1*0.70710678118654752f));
                    __half2 hv; hv.x = __float2half_rn(v0); hv.y = __float2half_rn(v1);
                    *(__half2*)(Ch + (size_t)row*N + col) = hv;
                } else {
                    if (EPI == 2){
                        v0 += bias[col]   + res[(size_t)row*N + col];
                        v1 += bias[col+1] + res[(size_t)row*N + col+1];
                    }
                    float2 v; v.x = v0; v.y = v1;
                    *(float2*)(C + (size_t)row*N + col) = v;
                }
            }
        }
    }
}

// ---------------- dt / dA from fp16 xn (exact fp32 dot, fp32 weights) ----------------
__global__ void dtda_kernel(const float* __restrict__ in_w,
                            const float* __restrict__ dt_bias,
                            const float* __restrict__ A_log){
    // 256 threads = 16 rows x 16 heads
    int row = blockIdx.x*16 + (threadIdx.x >> 4);
    int h = threadIdx.x & 15;
    const __half* xr = g_xn + (size_t)row*DMODEL;
    const float* wc = in_w + 2176 + h;   // column 2176+h, stride DPROJ
    float acc = dt_bias[h];
    #pragma unroll 8
    for (int k = 0; k < DMODEL; k++)
        acc += __half2float(xr[k]) * wc[(size_t)k*DPROJ];
    float dt = (acc > 20.f) ? acc : log1pf(__expf(acc));
    float dA = __expf(-__expf(A_log[h]) * dt);
    int b = row >> 12, t = row & (SEQL-1);
    size_t i0 = ((size_t)(b*2+0)*SEQL + t)*NHEADS + h;
    size_t i1 = ((size_t)(b*2+1)*SEQL + (SEQL-1-t))*NHEADS + h;
    g_dt[i0] = dt; g_dA[i0] = dA;
    g_dt[i1] = dt; g_dA[i1] = dA;
}

// ---------------- depthwise causal conv + silu (per direction) ----------------
__global__ void conv_kernel(const float* __restrict__ cw, const float* __restrict__ cb){
    size_t i = (size_t)blockIdx.x*blockDim.x + threadIdx.x;
    size_t total = (size_t)BATCH*2*SEQL*CONVDIM;
    if (i >= total) return;
    int c = (int)(i % CONVDIM);
    size_t r = i / CONVDIM;
    int s = (int)(r % SEQL);
    int bd = (int)(r / SEQL);
    int d = bd & 1, b = bd >> 1;
    float acc = cb[c];
    #pragma unroll
    for (int k=0;k<DCONV;k++){
        int u = s - (DCONV-1) + k;
        if (u >= 0){
            int t = d ? (SEQL-1-u) : u;
            acc += cw[k*CONVDIM + c] * g_zx[((size_t)(b*SEQL+t))*DPROJ_PAD + DINNER + c];
        }
    }
    g_conv[i] = siluf(acc);
}

// ---------------- selective scan: 64 CTAs (b,d,h), state in registers ----------------
#define CHUNK 16
#define NCHUNK (SEQL/CHUNK)

__global__ __launch_bounds__(256) void scan_kernel(const float* __restrict__ Dh){
    int bx = blockIdx.x;            // 0..63
    int h = bx & 15, d = (bx >> 4) & 1, b = bx >> 5;
    int tid = threadIdx.x;
    int p = tid >> 2, q = tid & 3;  // p: headdim row 0..63, q: state quarter

    __shared__ float buf[2][CHUNK][192];   // [xh 64][B 64][C 64]
    __shared__ float sdt[2][CHUNK], sdA[2][CHUNK];

    const float* base = g_conv + ((size_t)(b*2+d))*SEQL*CONVDIM;
    const float* dtb  = g_dt  + ((size_t)(b*2+d))*SEQL*NHEADS + h;
    const float* dab  = g_dA  + ((size_t)(b*2+d))*SEQL*NHEADS + h;
    float* ybase = g_y + ((size_t)(b*2+d))*SEQL*DINNER;

    float hreg[16];
    #pragma unroll
    for (int i=0;i<16;i++) hreg[i] = 0.f;
    float Dhh = Dh[h];

    auto issue = [&](int c, int sbuf){
        int s0 = c*CHUNK;
        #pragma unroll
        for (int rr=0;rr<3;rr++){
            int j = tid + rr*256;        // 0..767
            int step = j / 48;
            int seg = j % 48;
            int off = seg*4;             // float offset within 192
            const float* src;
            const float* rowp = base + (size_t)(s0+step)*CONVDIM;
            if (off < 64)       src = rowp + h*HEADDIM + off;
            else if (off < 128) src = rowp + DINNER + (off-64);
            else                src = rowp + DINNER + DSTATE + (off-128);
            cp16(&buf[sbuf][step][off], src);
        }
        if (tid < CHUNK)            cp4(&sdt[sbuf][tid],        dtb + (size_t)(s0+tid)*NHEADS);
        else if (tid < 2*CHUNK)     cp4(&sdA[sbuf][tid-CHUNK],  dab + (size_t)(s0+tid-CHUNK)*NHEADS);
        asm volatile("cp.async.commit_group;\n");
    };

    issue(0, 0);
    for (int c=0;c<NCHUNK;c++){
        int cur = c & 1, nxt = cur ^ 1;
        if (c+1 < NCHUNK){
            issue(c+1, nxt);
            asm volatile("cp.async.wait_group 1;\n");
        } else {
            asm volatile("cp.async.wait_group 0;\n");
        }
        __syncthreads();
        #pragma unroll 4
        for (int k=0;k<CHUNK;k++){
            const float* row = buf[cur][k];
            float dt = sdt[cur][k], dA = sdA[cur][k];
            float xh = row[p];
            float dtx = dt*xh;
            const float4* Bp4 = (const float4*)(row + 64 + q*16);
            const float4* Cp4 = (const float4*)(row + 128 + q*16);
            float bv[16], cv[16];
            #pragma unroll
            for (int v2=0; v2<4; v2++){
                float4 bb = Bp4[v2], cc = Cp4[v2];
                bv[4*v2+0]=bb.x; bv[4*v2+1]=bb.y; bv[4*v2+2]=bb.z; bv[4*v2+3]=bb.w;
                cv[4*v2+0]=cc.x; cv[4*v2+1]=cc.y; cv[4*v2+2]=cc.z; cv[4*v2+3]=cc.w;
            }
            float acc = 0.f;
            #pragma unroll
            for (int i=0;i<16;i++){
                hreg[i] = hreg[i]*dA + dtx*bv[i];
                acc += hreg[i]*cv[i];
            }
            acc += __shfl_xor_sync(0xffffffffu, acc, 1);
            acc += __shfl_xor_sync(0xffffffffu, acc, 2);
            if (q == 0){
                int s = c*CHUNK + k;
                int t = d ? (SEQL-1-s) : s;
                ybase[(size_t)t*DINNER + h*HEADDIM + p] = acc + Dhh*xh;
            }
        }
        __syncthreads();
    }
}

// ---------------- gate (silu(z)), per-direction RMS norm, combine -> fp16 ----------------
__global__ void gate_kernel(const float* __restrict__ mw){
    int row = blockIdx.x;            // 0..8191 (= b*SEQL + t)
    int b = row >> 12, t = row & (SEQL-1);
    const float* z  = g_zx + (size_t)row*DPROJ_PAD;           // cols 0..1024
    const float* y0 = g_y + ((size_t)(b*2+0)*SEQL + t)*DINNER;
    const float* y1 = g_y + ((size_t)(b*2+1)*SEQL + t)*DINNER;
    float g0[4], g1[4];
    float ss0 = 0.f, ss1 = 0.f;
    #pragma unroll
    for (int j=0;j<4;j++){
        int c = threadIdx.x + j*256;
        float zz = z[c];
        float sz = siluf(zz);
        g0[j] = y0[c]*sz; g1[j] = y1[c]*sz;
        ss0 += g0[j]*g0[j]; ss1 += g1[j]*g1[j];
    }
    #pragma unroll
    for (int o=16;o;o>>=1){
        ss0 += __shfl_xor_sync(0xffffffffu, ss0, o);
        ss1 += __shfl_xor_sync(0xffffffffu, ss1, o);
    }
    __shared__ float red[16];
    int wid = threadIdx.x >> 5, lane = threadIdx.x & 31;
    if (lane == 0){ red[wid] = ss0; red[8+wid] = ss1; }
    __syncthreads();
    if (threadIdx.x == 0){
        float a=0.f, bb=0.f;
        #pragma unroll
        for (int w=0;w<8;w++){ a += red[w]; bb += red[8+w]; }
        red[0] = a; red[8] = bb;
    }
    __syncthreads();
    float r0 = rsqrtf(red[0]*(1.f/DINNER) + EPS);
    float r1 = rsqrtf(red[8]*(1.f/DINNER) + EPS);
    __half* go = g_g + (size_t)row*DINNER;
    #pragma unroll
    for (int j=0;j<4;j++){
        int c = threadIdx.x + j*256;
        go[c] = __float2half_rn((g0[j]*r0 + g1[j]*r1) * mw[c]);
    }
}

// ---------------- launch ----------------
extern "C" void kernel_launch(void* const* d_in, const int* in_sizes, int n_in,
                              void* d_out, int out_size)
{
    const float* x        = (const float*)d_in[0];
    const float* nin_w    = (const float*)d_in[1];
    const float* nin_b    = (const float*)d_in[2];
    const float* nout_w   = (const float*)d_in[3];
    const float* nout_b   = (const float*)d_in[4];
    const float* in_w     = (const float*)d_in[5];
    const float* conv_w   = (const float*)d_in[6];
    const float* conv_b   = (const float*)d_in[7];
    const float* dt_bias  = (const float*)d_in[8];
    const float* A_log    = (const float*)d_in[9];
    const float* D_h      = (const float*)d_in[10];
    const float* mnorm_w  = (const float*)d_in[11];
    const float* out_w    = (const float*)d_in[12];
    const float* ff_w1    = (const float*)d_in[13];
    const float* ff_b1    = (const float*)d_in[14];
    const float* ff_w2    = (const float*)d_in[15];
    const float* ff_b2    = (const float*)d_in[16];
    float* out = (float*)d_out;

    float *p_zx, *p_mid;
    __half *p_xn, *p_g, *p_m, *p_ff1;
    __half *p_inwT, *p_outwT, *p_ff1T, *p_ff2T;
    cudaGetSymbolAddress((void**)&p_xn,   g_xn);
    cudaGetSymbolAddress((void**)&p_zx,   g_zx);
    cudaGetSymbolAddress((void**)&p_g,    g_g);
    cudaGetSymbolAddress((void**)&p_mid,  g_mid);
    cudaGetSymbolAddress((void**)&p_m,    g_m);
    cudaGetSymbolAddress((void**)&p_ff1,  g_ff1);
    cudaGetSymbolAddress((void**)&p_inwT, g_inwT);
    cudaGetSymbolAddress((void**)&p_outwT,g_outwT);
    cudaGetSymbolAddress((void**)&p_ff1T, g_ff1T);
    cudaGetSymbolAddress((void**)&p_ff2T, g_ff2T);

    dim3 tb32(32, 8);
    // 1. all weight transposes in one launch
    transpose_all_kernel<<<3712, tb32>>>(in_w, p_inwT, out_w, p_outwT,
                                         ff_w1, p_ff1T, ff_w2, p_ff2T);

    // 2. layernorm in (fp16 output)
    ln_kernel<<<ROWS/8, 256>>>(x, nin_w, nin_b, p_xn);

    // 3. dt/dA from fp16 xn (independent of GEMM)
    dtda_kernel<<<ROWS/16, 256>>>(in_w, dt_bias, A_log);

    // 4. in-proj: xn[8192,512] @ inwT[2304,512]^T -> zx[8192,2304] (fp32)
    mma_gemm<0><<<dim3(DPROJ_PAD/128, ROWS/128), 256>>>(
        p_xn, p_inwT, p_zx, nullptr, DMODEL, DPROJ_PAD, nullptr, nullptr);

    // 5. conv + silu (both directions)
    {
        size_t tot = (size_t)BATCH*2*SEQL*CONVDIM;
        conv_kernel<<<(unsigned)((tot+255)/256), 256>>>(conv_w, conv_b);
    }
    // 6. selective scan
    scan_kernel<<<BATCH*2*NHEADS, 256>>>(D_h);
    // 7. gate + per-dir rmsnorm + combine (fp16 out)
    gate_kernel<<<ROWS, 256>>>(mnorm_w);

    // 8. out-proj: g[8192,1024] @ outwT[512,1024]^T -> mid[8192,512] (fp32)
    mma_gemm<0><<<dim3(DMODEL/128, ROWS/128), 256>>>(
        p_g, p_outwT, p_mid, nullptr, DINNER, DMODEL, nullptr, nullptr);

    // 9. layernorm out (fp16 output)
    ln_kernel<<<ROWS/8, 256>>>(p_mid, nout_w, nout_b, p_m);

    // 10. FF1 + gelu: m[8192,512] @ ff1T[2048,512]^T -> ff1[8192,2048] (fp16 out)
    mma_gemm<1><<<dim3(DFF/128, ROWS/128), 256>>>(
        p_m, p_ff1T, nullptr, p_ff1, DMODEL, DFF, ff_b1, nullptr);

    // 11. FF2 + bias + residual(x): ff1[8192,2048] @ ff2T[512,2048]^T -> out[8192,512] (fp32)
    mma_gemm<2><<<dim3(DMODEL/128, ROWS/128), 256>>>(
        p_ff1, p_ff2T, out, nullptr, DFF, DMODEL, ff_b2, x);
}

// round 14
// speedup vs baseline: 2.0049x; 1.2225x over previous
#include <cuda_runtime.h>
#include <cuda_fp16.h>
#include <math.h>
#include <stdint.h>

// ---------------- problem constants ----------------
#define BATCH 2
#define SEQL 4096
#define DMODEL 512
#define DSTATE 64
#define DCONV 4
#define HEADDIM 64
#define DINNER 1024
#define NHEADS 16
#define CONVDIM 1152          // DINNER + 2*DSTATE
#define DPROJ 2192            // 2*DINNER + 2*DSTATE + NHEADS
#define DPROJ_PAD 2304        // padded to multiple of 128
#define ROWS (BATCH*SEQL)     // 8192
#define DFF 2048
#define EPS 1e-5f

// ---------------- scratch (static device mem; no allocations) ----------------
__device__ __half g_xn   [(size_t)ROWS*DMODEL];           // fp16 LN output (GEMM A + dtda)
__device__ float  g_zx   [(size_t)ROWS*DPROJ_PAD];
__device__ float  g_dt   [(size_t)BATCH*2*SEQL*NHEADS];
__device__ float  g_dA   [(size_t)BATCH*2*SEQL*NHEADS];
__device__ float  g_y    [(size_t)BATCH*2*SEQL*DINNER];   // indexed by ORIGINAL t
__device__ __half g_g    [(size_t)ROWS*DINNER];           // gated+rmsnormed (GEMM A)
__device__ float  g_mid  [(size_t)ROWS*DMODEL];
__device__ __half g_m    [(size_t)ROWS*DMODEL];           // LN output (GEMM A)
__device__ __half g_ff1  [(size_t)ROWS*DFF];              // gelu output (GEMM A)
// transposed weights [N, K] K-major, fp16
__device__ __half g_inwT [(size_t)DPROJ_PAD*DMODEL];
__device__ __half g_outwT[(size_t)DMODEL*DINNER];
__device__ __half g_ff1T [(size_t)DFF*DMODEL];
__device__ __half g_ff2T [(size_t)DMODEL*DFF];

// ---------------- helpers ----------------
// silu via single-MUFU tanh: x*sigmoid(x) = 0.5x*(1+tanh(x/2))
__device__ __forceinline__ float siluf(float x){
    float t;
    asm("tanh.approx.f32 %0, %1;" : "=f"(t) : "f"(0.5f*x));
    return 0.5f*x*(1.f + t);
}

__device__ __forceinline__ uint32_t smem_u32(const void* p){
    uint32_t a;
    asm("{ .reg .u64 t; cvta.to.shared.u64 t, %1; cvt.u32.u64 %0, t; }" : "=r"(a) : "l"(p));
    return a;
}
__device__ __forceinline__ void cp16(void* smem, const void* g){
    unsigned a = smem_u32(smem);
    asm volatile("cp.async.cg.shared.global [%0], [%1], 16;\n" :: "r"(a), "l"(g));
}
__device__ __forceinline__ void cp4(void* smem, const void* g){
    unsigned a = smem_u32(smem);
    asm volatile("cp.async.ca.shared.global [%0], [%1], 4;\n" :: "r"(a), "l"(g));
}

__device__ __forceinline__ void mma_f16(float* d, const uint32_t* a, const uint32_t* b){
    asm volatile(
        "mma.sync.aligned.m16n8k16.row.col.f32.f16.f16.f32 "
        "{%0,%1,%2,%3}, {%4,%5,%6,%7}, {%8,%9}, {%0,%1,%2,%3};"
        : "+f"(d[0]), "+f"(d[1]), "+f"(d[2]), "+f"(d[3])
        : "r"(a[0]), "r"(a[1]), "r"(a[2]), "r"(a[3]), "r"(b[0]), "r"(b[1]));
}

// ---------------- prep: batched weight transpose + input layernorm, one launch ----------------
// blocks [0,3712): transpose tiles ; [3712,4736): ln rows (8 per block)
__global__ __launch_bounds__(256) void prep_kernel(
    const float* __restrict__ in_w,  const float* __restrict__ out_w,
    const float* __restrict__ ff_w1, const float* __restrict__ ff_w2,
    const float* __restrict__ x, const float* __restrict__ nin_w,
    const float* __restrict__ nin_b)
{
    __shared__ float t[32][33];
    int tid = threadIdx.x;
    if (blockIdx.x < 3712){
        int tile = blockIdx.x;
        const float* in; __half* out; int K, N0, ktiles;
        if (tile < 1152){                    in = in_w;  out = g_inwT;  K = DMODEL; N0 = DPROJ;  ktiles = 16; }
        else if (tile < 1664){ tile -= 1152; in = out_w; out = g_outwT; K = DINNER; N0 = DMODEL; ktiles = 32; }
        else if (tile < 2688){ tile -= 1664; in = ff_w1; out = g_ff1T;  K = DMODEL; N0 = DFF;    ktiles = 16; }
        else {                 tile -= 2688; in = ff_w2; out = g_ff2T;  K = DFF;    N0 = DMODEL; ktiles = 64; }
        int kb = (tile % ktiles)*32, nb = (tile / ktiles)*32;
        int xx = tid & 31, yy = tid >> 5;
        #pragma unroll
        for (int i=0;i<32;i+=8){
            int k = kb + yy + i, n = nb + xx;
            t[yy+i][xx] = (n < N0) ? in[(size_t)k*N0 + n] : 0.f;
        }
        __syncthreads();
        #pragma unroll
        for (int i=0;i<32;i+=8){
            int n = nb + yy + i, k = kb + xx;
            out[(size_t)n*K + k] = __float2half_rn(t[xx][yy+i]);
        }
    } else {
        int row = (blockIdx.x - 3712)*8 + (tid>>5);
        int lane = tid & 31;
        const float* xr = x + (size_t)row*DMODEL;
        float v[16]; float s = 0.f;
        #pragma unroll
        for (int i=0;i<16;i++){ v[i] = xr[lane + 32*i]; s += v[i]; }
        #pragma unroll
        for (int o=16;o;o>>=1) s += __shfl_xor_sync(0xffffffffu, s, o);
        float mu = s * (1.f/DMODEL);
        float s2 = 0.f;
        #pragma unroll
        for (int i=0;i<16;i++){ float d = v[i]-mu; s2 += d*d; }
        #pragma unroll
        for (int o=16;o;o>>=1) s2 += __shfl_xor_sync(0xffffffffu, s2, o);
        float inv = rsqrtf(s2*(1.f/DMODEL) + EPS);
        __half* orow = g_xn + (size_t)row*DMODEL;
        #pragma unroll
        for (int i=0;i<16;i++){
            int c = lane + 32*i;
            orow[c] = __float2half_rn((v[i]-mu)*inv*nin_w[c] + nin_b[c]);
        }
    }
}

// ---------------- layernorm (warp per 512-row), fp16 output (used for ln_out) ----------------
__global__ void ln_kernel(const float* __restrict__ x, const float* __restrict__ w,
                          const float* __restrict__ b, __half* __restrict__ out){
    int row = blockIdx.x*(blockDim.x>>5) + (threadIdx.x>>5);
    int lane = threadIdx.x & 31;
    if (row >= ROWS) return;
    const float* xr = x + (size_t)row*DMODEL;
    float v[16]; float s = 0.f;
    #pragma unroll
    for (int i=0;i<16;i++){ v[i] = xr[lane + 32*i]; s += v[i]; }
    #pragma unroll
    for (int o=16;o;o>>=1) s += __shfl_xor_sync(0xffffffffu, s, o);
    float mu = s * (1.f/DMODEL);
    float s2 = 0.f;
    #pragma unroll
    for (int i=0;i<16;i++){ float d = v[i]-mu; s2 += d*d; }
    #pragma unroll
    for (int o=16;o;o>>=1) s2 += __shfl_xor_sync(0xffffffffu, s2, o);
    float inv = rsqrtf(s2*(1.f/DMODEL) + EPS);
    __half* orow = out + (size_t)row*DMODEL;
    #pragma unroll
    for (int i=0;i<16;i++){
        int c = lane + 32*i;
        orow[c] = __float2half_rn((v[i]-mu)*inv*w[c] + b[c]);
    }
}

// ---------------- fp16 mma.sync GEMM: C[M,N] = A[M,K] @ B[N,K]^T (fp32 accum) ----------------
#define GSTAGES 4
#define HROWSTR 24
#define HSTAGE_H (128*HROWSTR)

template<int EPI>
__global__ __launch_bounds__(256) void mma_gemm(
    const __half* __restrict__ A, const __half* __restrict__ Bw,
    float* __restrict__ C, __half* __restrict__ Ch,
    int K, int N, const float* __restrict__ bias, const float* __restrict__ res)
{
    __shared__ __half sA[GSTAGES][HSTAGE_H];
    __shared__ __half sB[GSTAGES][HSTAGE_H];

    int tid = threadIdx.x, lane = tid & 31, wid = tid >> 5;
    int bm = blockIdx.y * 128, bn = blockIdx.x * 128;
    int wm = (wid >> 1) * 32, wn = (wid & 1) * 64;
    int grp = lane >> 2, tig = lane & 3;

    float acc[2][8][4];
    #pragma unroll
    for (int mi=0;mi<2;mi++)
        #pragma unroll
        for (int ni=0;ni<8;ni++)
            #pragma unroll
            for (int u=0;u<4;u++) acc[mi][ni][u] = 0.f;

    int lrow = tid >> 1, lc = tid & 1;     // 128 rows x 2 16B-chunks
    auto load = [&](int st, int k0){
        cp16(&sA[st][lrow*HROWSTR + lc*8], A + (size_t)(bm+lrow)*K + k0 + lc*8);
        cp16(&sB[st][lrow*HROWSTR + lc*8], Bw + (size_t)(bn+lrow)*K + k0 + lc*8);
        asm volatile("cp.async.commit_group;\n");
    };

    int nk = K >> 4;
    #pragma unroll
    for (int s=0;s<GSTAGES-1;s++) load(s, s << 4);

    for (int kt = 0; kt < nk; kt++){
        asm volatile("cp.async.wait_group %0;\n" :: "n"(GSTAGES-2));
        __syncthreads();
        int nx = kt + GSTAGES - 1;
        if (nx < nk) load(nx % GSTAGES, nx << 4);
        else         asm volatile("cp.async.commit_group;\n");

        const __half* as = sA[kt % GSTAGES];
        const __half* bs = sB[kt % GSTAGES];
        uint32_t af[2][4], bf[8][2];
        #pragma unroll
        for (int mi=0;mi<2;mi++){
            int r = wm + mi*16 + grp;
            af[mi][0] = *(const uint32_t*)&as[r*HROWSTR     + tig*2];
            af[mi][1] = *(const uint32_t*)&as[(r+8)*HROWSTR + tig*2];
            af[mi][2] = *(const uint32_t*)&as[r*HROWSTR     + tig*2 + 8];
            af[mi][3] = *(const uint32_t*)&as[(r+8)*HROWSTR + tig*2 + 8];
        }
        #pragma unroll
        for (int ni=0;ni<8;ni++){
            int c0 = wn + ni*8 + grp;
            bf[ni][0] = *(const uint32_t*)&bs[c0*HROWSTR + tig*2];
            bf[ni][1] = *(const uint32_t*)&bs[c0*HROWSTR + tig*2 + 8];
        }
        #pragma unroll
        for (int mi=0;mi<2;mi++)
            #pragma unroll
            for (int ni=0;ni<8;ni++)
                mma_f16(acc[mi][ni], af[mi], bf[ni]);
        // (bottom barrier removed: top barrier at next iter protects stage reuse)
    }

    #pragma unroll
    for (int mi=0;mi<2;mi++){
        #pragma unroll
        for (int half2_=0; half2_<2; half2_++){
            int row = bm + wm + mi*16 + grp + half2_*8;
            #pragma unroll
            for (int ni=0;ni<8;ni++){
                int col = bn + wn + ni*8 + tig*2;
                float v0 = acc[mi][ni][half2_*2+0];
                float v1 = acc[mi][ni][half2_*2+1];
                if (EPI == 1){
                    v0 += bias[col];   v1 += bias[col+1];
                    v0 = 0.5f*v0*(1.f + erff(v0*0.70710678118654752f));
                    v1 = 0.5f*v1*(1.f + erff(v1*0.70710678118654752f));
                    __half2 hv; hv.x = __float2half_rn(v0); hv.y = __float2half_rn(v1);
                    *(__half2*)(Ch + (size_t)row*N + col) = hv;
                } else {
                    if (EPI == 2){
                        v0 += bias[col]   + res[(size_t)row*N + col];
                        v1 += bias[col+1] + res[(size_t)row*N + col+1];
                    }
                    float2 v; v.x = v0; v.y = v1;
                    *(float2*)(C + (size_t)row*N + col) = v;
                }
            }
        }
    }
}

// ---------------- dt / dA from fp16 xn (exact fp32 dot, fp32 weights) ----------------
__global__ void dtda_kernel(const float* __restrict__ in_w,
                            const float* __restrict__ dt_bias,
                            const float* __restrict__ A_log){
    int row = blockIdx.x*16 + (threadIdx.x >> 4);
    int h = threadIdx.x & 15;
    const __half* xr = g_xn + (size_t)row*DMODEL;
    const float* wc = in_w + 2176 + h;
    float acc = dt_bias[h];
    #pragma unroll 8
    for (int k = 0; k < DMODEL; k++)
        acc += __half2float(xr[k]) * wc[(size_t)k*DPROJ];
    float dt = (acc > 20.f) ? acc : log1pf(__expf(acc));
    float dA = __expf(-__expf(A_log[h]) * dt);
    int b = row >> 12, t = row & (SEQL-1);
    size_t i0 = ((size_t)(b*2+0)*SEQL + t)*NHEADS + h;
    size_t i1 = ((size_t)(b*2+1)*SEQL + (SEQL-1-t))*NHEADS + h;
    g_dt[i0] = dt; g_dA[i0] = dA;
    g_dt[i1] = dt; g_dA[i1] = dA;
}

// ---------------- selective scan w/ fused conv+silu ----------------
// 128 CTAs: (b, d, h, half). Each CTA: 32 headdim rows x 64 states.
// thread: p = tid>>3 (row 0..31), q = tid&7 (8 states each)
#define CHUNK 16
#define NCHUNK (SEQL/CHUNK)
#define NCH 160              // 32 x-chans + 64 B + 64 C
#define RROWS 19             // CHUNK + DCONV - 1

__global__ __launch_bounds__(256) void scan2_kernel(const float* __restrict__ Dh,
                                                    const float* __restrict__ cw,
                                                    const float* __restrict__ cb){
    int bx = blockIdx.x;            // 0..127
    int half = bx & 1, h = (bx >> 1) & 15, d = (bx >> 5) & 1, b = bx >> 6;
    int tid = threadIdx.x;
    int p = tid >> 3, q = tid & 7;

    __shared__ float sraw[2][RROWS][NCH];
    __shared__ float sconv[CHUNK][NCH];
    __shared__ float scw[4][NCH];
    __shared__ float scb[NCH];
    __shared__ float sdt[2][CHUNK], sdA[2][CHUNK];

    // preload conv weights for this CTA's channels (CONVDIM space)
    for (int ch = tid; ch < NCH; ch += 256){
        int cc = ch < 32 ? h*64 + half*32 + ch
               : (ch < 96 ? 1024 + (ch-32) : 1088 + (ch-96));
        scb[ch] = cb[cc];
        #pragma unroll
        for (int k=0;k<4;k++) scw[k][ch] = cw[k*CONVDIM + cc];
    }
    // zero boundary rows (u<0) of buffer 0
    for (int j = tid; j < 3*NCH; j += 256) (&sraw[0][0][0])[j] = 0.f;
    __syncthreads();

    const float* zxb = g_zx + (size_t)b*SEQL*DPROJ_PAD;
    const float* dtb = g_dt + ((size_t)(b*2+d))*SEQL*NHEADS + h;
    const float* dab = g_dA + ((size_t)(b*2+d))*SEQL*NHEADS + h;
    float* ybase = g_y + ((size_t)(b*2+d))*SEQL*DINNER;
    int ycol = h*HEADDIM + half*32 + p;

    float hreg[8];
    #pragma unroll
    for (int i=0;i<8;i++) hreg[i] = 0.f;
    float Dhh = Dh[h];

    auto issue = [&](int c, int sbuf){
        int s0 = c*CHUNK;
        #pragma unroll
        for (int it=0; it<3; it++){
            int j = tid + it*256;            // 0..767 ; 760 = 19*40 cp16 ops
            if (j < RROWS*40){
                int r = j / 40, seg = j % 40;
                int off = seg*4;
                int u = s0 - 3 + r;
                if (u >= 0){
                    int t = d ? (SEQL-1-u) : u;
                    const float* rowp = zxb + (size_t)t*DPROJ_PAD;
                    const float* src;
                    if (off < 32)      src = rowp + 1024 + h*64 + half*32 + off;
                    else if (off < 96) src = rowp + 2048 + (off-32);
                    else               src = rowp + 2112 + (off-96);
                    cp16(&sraw[sbuf][r][off], src);
                }
            }
        }
        if (tid < CHUNK)            cp4(&sdt[sbuf][tid],        dtb + (size_t)(s0+tid)*NHEADS);
        else if (tid < 2*CHUNK)     cp4(&sdA[sbuf][tid-CHUNK],  dab + (size_t)(s0+tid-CHUNK)*NHEADS);
        asm volatile("cp.async.commit_group;\n");
    };

    issue(0, 0);
    for (int c=0;c<NCHUNK;c++){
        int cur = c & 1, nxt = cur ^ 1;
        asm volatile("cp.async.wait_group 0;\n");
        __syncthreads();                    // raw[cur]+dt ready; prev-iter readers done
        if (c+1 < NCHUNK) issue(c+1, nxt);  // overlaps conv+scan below
        // conv + silu into sconv: 16*160 = 2560 outputs
        #pragma unroll
        for (int it=0; it<10; it++){
            int j = tid + it*256;
            int st = j / NCH, ch = j - st*NCH;
            float a = scb[ch];
            #pragma unroll
            for (int k=0;k<4;k++) a += scw[k][ch]*sraw[cur][st+k][ch];
            sconv[st][ch] = siluf(a);
        }
        __syncthreads();
        #pragma unroll 4
        for (int k=0;k<CHUNK;k++){
            const float* row = sconv[k];
            float dt = sdt[cur][k], dA = sdA[cur][k];
            float xh = row[p];
            float dtx = dt*xh;
            const float4* Bp4 = (const float4*)(row + 32 + q*8);
            const float4* Cp4 = (const float4*)(row + 96 + q*8);
            float4 b0 = Bp4[0], b1 = Bp4[1];
            float4 c0 = Cp4[0], c1 = Cp4[1];
            float bv[8] = {b0.x,b0.y,b0.z,b0.w,b1.x,b1.y,b1.z,b1.w};
            float cv[8] = {c0.x,c0.y,c0.z,c0.w,c1.x,c1.y,c1.z,c1.w};
            float acc = 0.f;
            #pragma unroll
            for (int i=0;i<8;i++){
                hreg[i] = hreg[i]*dA + dtx*bv[i];
                acc += hreg[i]*cv[i];
            }
            acc += __shfl_xor_sync(0xffffffffu, acc, 1);
            acc += __shfl_xor_sync(0xffffffffu, acc, 2);
            acc += __shfl_xor_sync(0xffffffffu, acc, 4);
            if (q == 0){
                int s = c*CHUNK + k;
                int t = d ? (SEQL-1-s) : s;
                ybase[(size_t)t*DINNER + ycol] = acc + Dhh*xh;
            }
        }
    }
}

// ---------------- gate (silu(z)), per-direction RMS norm, combine -> fp16 ----------------
__global__ void gate_kernel(const float* __restrict__ mw){
    int row = blockIdx.x;
    int b = row >> 12, t = row & (SEQL-1);
    const float* z  = g_zx + (size_t)row*DPROJ_PAD;
    const float* y0 = g_y + ((size_t)(b*2+0)*SEQL + t)*DINNER;
    const float* y1 = g_y + ((size_t)(b*2+1)*SEQL + t)*DINNER;
    float g0[4], g1[4];
    float ss0 = 0.f, ss1 = 0.f;
    #pragma unroll
    for (int j=0;j<4;j++){
        int c = threadIdx.x + j*256;
        float zz = z[c];
        float sz = siluf(zz);
        g0[j] = y0[c]*sz; g1[j] = y1[c]*sz;
        ss0 += g0[j]*g0[j]; ss1 += g1[j]*g1[j];
    }
    #pragma unroll
    for (int o=16;o;o>>=1){
        ss0 += __shfl_xor_sync(0xffffffffu, ss0, o);
        ss1 += __shfl_xor_sync(0xffffffffu, ss1, o);
    }
    __shared__ float red[16];
    int wid = threadIdx.x >> 5, lane = threadIdx.x & 31;
    if (lane == 0){ red[wid] = ss0; red[8+wid] = ss1; }
    __syncthreads();
    if (threadIdx.x == 0){
        float a=0.f, bb=0.f;
        #pragma unroll
        for (int w=0;w<8;w++){ a += red[w]; bb += red[8+w]; }
        red[0] = a; red[8] = bb;
    }
    __syncthreads();
    float r0 = rsqrtf(red[0]*(1.f/DINNER) + EPS);
    float r1 = rsqrtf(red[8]*(1.f/DINNER) + EPS);
    __half* go = g_g + (size_t)row*DINNER;
    #pragma unroll
    for (int j=0;j<4;j++){
        int c = threadIdx.x + j*256;
        go[c] = __float2half_rn((g0[j]*r0 + g1[j]*r1) * mw[c]);
    }
}

// ---------------- launch ----------------
extern "C" void kernel_launch(void* const* d_in, const int* in_sizes, int n_in,
                              void* d_out, int out_size)
{
    const float* x        = (const float*)d_in[0];
    const float* nin_w    = (const float*)d_in[1];
    const float* nin_b    = (const float*)d_in[2];
    const float* nout_w   = (const float*)d_in[3];
    const float* nout_b   = (const float*)d_in[4];
    const float* in_w     = (const float*)d_in[5];
    const float* conv_w   = (const float*)d_in[6];
    const float* conv_b   = (const float*)d_in[7];
    const float* dt_bias  = (const float*)d_in[8];
    const float* A_log    = (const float*)d_in[9];
    const float* D_h      = (const float*)d_in[10];
    const float* mnorm_w  = (const float*)d_in[11];
    const float* out_w    = (const float*)d_in[12];
    const float* ff_w1    = (const float*)d_in[13];
    const float* ff_b1    = (const float*)d_in[14];
    const float* ff_w2    = (const float*)d_in[15];
    const float* ff_b2    = (const float*)d_in[16];
    float* out = (float*)d_out;

    float *p_zx, *p_mid;
    __half *p_xn, *p_g, *p_m, *p_ff1;
    __half *p_inwT, *p_outwT, *p_ff1T, *p_ff2T;
    cudaGetSymbolAddress((void**)&p_xn,   g_xn);
    cudaGetSymbolAddress((void**)&p_zx,   g_zx);
    cudaGetSymbolAddress((void**)&p_g,    g_g);
    cudaGetSymbolAddress((void**)&p_mid,  g_mid);
    cudaGetSymbolAddress((void**)&p_m,    g_m);
    cudaGetSymbolAddress((void**)&p_ff1,  g_ff1);
    cudaGetSymbolAddress((void**)&p_inwT, g_inwT);
    cudaGetSymbolAddress((void**)&p_outwT,g_outwT);
    cudaGetSymbolAddress((void**)&p_ff1T, g_ff1T);
    cudaGetSymbolAddress((void**)&p_ff2T, g_ff2T);

    // 1. prep: all weight transposes + input layernorm
    prep_kernel<<<4736, 256>>>(in_w, out_w, ff_w1, ff_w2, x, nin_w, nin_b);

    // 2. in-proj: xn[8192,512] @ inwT[2304,512]^T -> zx[8192,2304]
    mma_gemm<0><<<dim3(DPROJ_PAD/128, ROWS/128), 256>>>(
        p_xn, p_inwT, p_zx, nullptr, DMODEL, DPROJ_PAD, nullptr, nullptr);

    // 3. dt/dA (exact fp32)
    dtda_kernel<<<ROWS/16, 256>>>(in_w, dt_bias, A_log);

    // 4. scan with fused conv+silu  (<- ncu capture slot)
    scan2_kernel<<<128, 256>>>(D_h, conv_w, conv_b);

    // 5. gate + per-dir rmsnorm + combine (fp16 out)
    gate_kernel<<<ROWS, 256>>>(mnorm_w);

    // 6. out-proj: g[8192,1024] @ outwT[512,1024]^T -> mid[8192,512]
    mma_gemm<0><<<dim3(DMODEL/128, ROWS/128), 256>>>(
        p_g, p_outwT, p_mid, nullptr, DINNER, DMODEL, nullptr, nullptr);

    // 7. layernorm out (fp16)
    ln_kernel<<<ROWS/8, 256>>>(p_mid, nout_w, nout_b, p_m);

    // 8. FF1 + gelu -> fp16
    mma_gemm<1><<<dim3(DFF/128, ROWS/128), 256>>>(
        p_m, p_ff1T, nullptr, p_ff1, DMODEL, DFF, ff_b1, nullptr);

    // 9. FF2 + bias + residual(x)
    mma_gemm<2><<<dim3(DMODEL/128, ROWS/128), 256>>>(
        p_ff1, p_ff2T, out, nullptr, DFF, DMODEL, ff_b2, x);
}

// round 16
// speedup vs baseline: 2.3227x; 1.1585x over previous
#include <cuda_runtime.h>
#include <cuda_fp16.h>
#include <math.h>
#include <stdint.h>

// ---------------- problem constants ----------------
#define BATCH 2
#define SEQL 4096
#define DMODEL 512
#define DSTATE 64
#define DCONV 4
#define HEADDIM 64
#define DINNER 1024
#define NHEADS 16
#define CONVDIM 1152          // DINNER + 2*DSTATE
#define DPROJ 2192            // 2*DINNER + 2*DSTATE + NHEADS
#define DPROJ_PAD 2304        // padded to multiple of 128
#define ROWS (BATCH*SEQL)     // 8192
#define DFF 2048
#define EPS 1e-5f

// ---------------- scratch (static device mem; no allocations) ----------------
__device__ __half g_xn   [(size_t)ROWS*DMODEL];           // fp16 LN output (GEMM A + dtda)
__device__ float  g_zx   [(size_t)ROWS*DPROJ_PAD];
__device__ float  g_dt   [(size_t)BATCH*2*SEQL*NHEADS];
__device__ float  g_dA   [(size_t)BATCH*2*SEQL*NHEADS];
__device__ float  g_y    [(size_t)BATCH*2*SEQL*DINNER];   // indexed by ORIGINAL t
__device__ __half g_g    [(size_t)ROWS*DINNER];           // gated+rmsnormed (GEMM A)
__device__ float  g_mid  [(size_t)ROWS*DMODEL];
__device__ __half g_m    [(size_t)ROWS*DMODEL];           // LN output (GEMM A)
__device__ __half g_ff1  [(size_t)ROWS*DFF];              // gelu output (GEMM A)
// transposed weights [N, K] K-major, fp16
__device__ __half g_inwT [(size_t)DPROJ_PAD*DMODEL];
__device__ __half g_outwT[(size_t)DMODEL*DINNER];
__device__ __half g_ff1T [(size_t)DFF*DMODEL];
__device__ __half g_ff2T [(size_t)DMODEL*DFF];

// ---------------- helpers ----------------
__device__ __forceinline__ float siluf(float x){
    float t;
    asm("tanh.approx.f32 %0, %1;" : "=f"(t) : "f"(0.5f*x));
    return 0.5f*x*(1.f + t);
}

__device__ __forceinline__ uint32_t smem_u32(const void* p){
    uint32_t a;
    asm("{ .reg .u64 t; cvta.to.shared.u64 t, %1; cvt.u32.u64 %0, t; }" : "=r"(a) : "l"(p));
    return a;
}
__device__ __forceinline__ void cp16(void* smem, const void* g){
    unsigned a = smem_u32(smem);
    asm volatile("cp.async.cg.shared.global [%0], [%1], 16;\n" :: "r"(a), "l"(g));
}
__device__ __forceinline__ void cp4(void* smem, const void* g){
    unsigned a = smem_u32(smem);
    asm volatile("cp.async.ca.shared.global [%0], [%1], 4;\n" :: "r"(a), "l"(g));
}

__device__ __forceinline__ void mma_f16(float* d, const uint32_t* a, const uint32_t* b){
    asm volatile(
        "mma.sync.aligned.m16n8k16.row.col.f32.f16.f16.f32 "
        "{%0,%1,%2,%3}, {%4,%5,%6,%7}, {%8,%9}, {%0,%1,%2,%3};"
        : "+f"(d[0]), "+f"(d[1]), "+f"(d[2]), "+f"(d[3])
        : "r"(a[0]), "r"(a[1]), "r"(a[2]), "r"(a[3]), "r"(b[0]), "r"(b[1]));
}

// ---------------- prep: batched weight transpose + input layernorm, one launch ----------------
__global__ __launch_bounds__(256) void prep_kernel(
    const float* __restrict__ in_w,  const float* __restrict__ out_w,
    const float* __restrict__ ff_w1, const float* __restrict__ ff_w2,
    const float* __restrict__ x, const float* __restrict__ nin_w,
    const float* __restrict__ nin_b)
{
    __shared__ float t[32][33];
    int tid = threadIdx.x;
    if (blockIdx.x < 3712){
        int tile = blockIdx.x;
        const float* in; __half* out; int K, N0, ktiles;
        if (tile < 1152){                    in = in_w;  out = g_inwT;  K = DMODEL; N0 = DPROJ;  ktiles = 16; }
        else if (tile < 1664){ tile -= 1152; in = out_w; out = g_outwT; K = DINNER; N0 = DMODEL; ktiles = 32; }
        else if (tile < 2688){ tile -= 1664; in = ff_w1; out = g_ff1T;  K = DMODEL; N0 = DFF;    ktiles = 16; }
        else {                 tile -= 2688; in = ff_w2; out = g_ff2T;  K = DFF;    N0 = DMODEL; ktiles = 64; }
        int kb = (tile % ktiles)*32, nb = (tile / ktiles)*32;
        int xx = tid & 31, yy = tid >> 5;
        #pragma unroll
        for (int i=0;i<32;i+=8){
            int k = kb + yy + i, n = nb + xx;
            t[yy+i][xx] = (n < N0) ? in[(size_t)k*N0 + n] : 0.f;
        }
        __syncthreads();
        #pragma unroll
        for (int i=0;i<32;i+=8){
            int n = nb + yy + i, k = kb + xx;
            out[(size_t)n*K + k] = __float2half_rn(t[xx][yy+i]);
        }
    } else {
        int row = (blockIdx.x - 3712)*8 + (tid>>5);
        int lane = tid & 31;
        const float* xr = x + (size_t)row*DMODEL;
        float v[16]; float s = 0.f;
        #pragma unroll
        for (int i=0;i<16;i++){ v[i] = xr[lane + 32*i]; s += v[i]; }
        #pragma unroll
        for (int o=16;o;o>>=1) s += __shfl_xor_sync(0xffffffffu, s, o);
        float mu = s * (1.f/DMODEL);
        float s2 = 0.f;
        #pragma unroll
        for (int i=0;i<16;i++){ float d = v[i]-mu; s2 += d*d; }
        #pragma unroll
        for (int o=16;o;o>>=1) s2 += __shfl_xor_sync(0xffffffffu, s2, o);
        float inv = rsqrtf(s2*(1.f/DMODEL) + EPS);
        __half* orow = g_xn + (size_t)row*DMODEL;
        #pragma unroll
        for (int i=0;i<16;i++){
            int c = lane + 32*i;
            orow[c] = __float2half_rn((v[i]-mu)*inv*nin_w[c] + nin_b[c]);
        }
    }
}

// ---------------- layernorm (warp per 512-row), fp16 output ----------------
__global__ void ln_kernel(const float* __restrict__ x, const float* __restrict__ w,
                          const float* __restrict__ b, __half* __restrict__ out){
    int row = blockIdx.x*(blockDim.x>>5) + (threadIdx.x>>5);
    int lane = threadIdx.x & 31;
    if (row >= ROWS) return;
    const float* xr = x + (size_t)row*DMODEL;
    float v[16]; float s = 0.f;
    #pragma unroll
    for (int i=0;i<16;i++){ v[i] = xr[lane + 32*i]; s += v[i]; }
    #pragma unroll
    for (int o=16;o;o>>=1) s += __shfl_xor_sync(0xffffffffu, s, o);
    float mu = s * (1.f/DMODEL);
    float s2 = 0.f;
    #pragma unroll
    for (int i=0;i<16;i++){ float d = v[i]-mu; s2 += d*d; }
    #pragma unroll
    for (int o=16;o;o>>=1) s2 += __shfl_xor_sync(0xffffffffu, s2, o);
    float inv = rsqrtf(s2*(1.f/DMODEL) + EPS);
    __half* orow = out + (size_t)row*DMODEL;
    #pragma unroll
    for (int i=0;i<16;i++){
        int c = lane + 32*i;
        orow[c] = __float2half_rn((v[i]-mu)*inv*w[c] + b[c]);
    }
}

// ---------------- fp16 mma.sync GEMM: C[M,N] = A[M,K] @ B[N,K]^T (fp32 accum) ----------------
// BM=128, BN=128, BK=16, 256 threads (8 warps 4x2, warp tile 32x64)
// 6-stage cp.async pipeline, TWO K-steps per barrier (fixed costs halved).
// group index == kt always (empty commits at tail keep accounting).
#define GST 6
#define HROWSTR 24
#define HSTAGE_H (128*HROWSTR)
#define GSMEM_BYTES (2*GST*HSTAGE_H*2)     // 73728

template<int EPI>
__global__ __launch_bounds__(256) void mma_gemm(
    const __half* __restrict__ A, const __half* __restrict__ Bw,
    float* __restrict__ C, __half* __restrict__ Ch,
    int K, int N, const float* __restrict__ bias, const float* __restrict__ res)
{
    extern __shared__ __half hsm[];
    __half* sAb = hsm;
    __half* sBb = hsm + GST*HSTAGE_H;

    int tid = threadIdx.x, lane = tid & 31, wid = tid >> 5;
    int bm = blockIdx.y * 128, bn = blockIdx.x * 128;
    int wm = (wid >> 1) * 32, wn = (wid & 1) * 64;
    int grp = lane >> 2, tig = lane & 3;

    float acc[2][8][4];
    #pragma unroll
    for (int mi=0;mi<2;mi++)
        #pragma unroll
        for (int ni=0;ni<8;ni++)
            #pragma unroll
            for (int u=0;u<4;u++) acc[mi][ni][u] = 0.f;

    int lrow = tid >> 1, lc = tid & 1;
    auto load = [&](int st, int k0){
        cp16(&sAb[st*HSTAGE_H + lrow*HROWSTR + lc*8], A + (size_t)(bm+lrow)*K + k0 + lc*8);
        cp16(&sBb[st*HSTAGE_H + lrow*HROWSTR + lc*8], Bw + (size_t)(bn+lrow)*K + k0 + lc*8);
        asm volatile("cp.async.commit_group;\n");
    };

    int nk = K >> 4;          // even (>= 32)
    #pragma unroll
    for (int s=0;s<4;s++) load(s, s << 4);

    int nk2 = nk >> 1;
    for (int it = 0; it < nk2; it++){
        asm volatile("cp.async.wait_group 2;\n");
        __syncthreads();
        int kt0 = it*2;
        int nx = kt0 + 4;
        if (nx < nk) load(nx % GST, nx << 4);
        else         asm volatile("cp.async.commit_group;\n");
        if (nx+1 < nk) load((nx+1) % GST, (nx+1) << 4);
        else           asm volatile("cp.async.commit_group;\n");

        #pragma unroll
        for (int s2 = 0; s2 < 2; s2++){
            const __half* as = sAb + ((kt0+s2) % GST)*HSTAGE_H;
            const __half* bs = sBb + ((kt0+s2) % GST)*HSTAGE_H;
            uint32_t af[2][4], bf[8][2];
            #pragma unroll
            for (int mi=0;mi<2;mi++){
                int r = wm + mi*16 + grp;
                af[mi][0] = *(const uint32_t*)&as[r*HROWSTR     + tig*2];
                af[mi][1] = *(const uint32_t*)&as[(r+8)*HROWSTR + tig*2];
                af[mi][2] = *(const uint32_t*)&as[r*HROWSTR     + tig*2 + 8];
                af[mi][3] = *(const uint32_t*)&as[(r+8)*HROWSTR + tig*2 + 8];
            }
            #pragma unroll
            for (int ni=0;ni<8;ni++){
                int c0 = wn + ni*8 + grp;
                bf[ni][0] = *(const uint32_t*)&bs[c0*HROWSTR + tig*2];
                bf[ni][1] = *(const uint32_t*)&bs[c0*HROWSTR + tig*2 + 8];
            }
            #pragma unroll
            for (int mi=0;mi<2;mi++)
                #pragma unroll
                for (int ni=0;ni<8;ni++)
                    mma_f16(acc[mi][ni], af[mi], bf[ni]);
        }
    }

    #pragma unroll
    for (int mi=0;mi<2;mi++){
        #pragma unroll
        for (int half2_=0; half2_<2; half2_++){
            int row = bm + wm + mi*16 + grp + half2_*8;
            #pragma unroll
            for (int ni=0;ni<8;ni++){
                int col = bn + wn + ni*8 + tig*2;
                float v0 = acc[mi][ni][half2_*2+0];
                float v1 = acc[mi][ni][half2_*2+1];
                if (EPI == 1){
                    v0 += bias[col];   v1 += bias[col+1];
                    v0 = 0.5f*v0*(1.f + erff(v0*0.70710678118654752f));
                    v1 = 0.5f*v1*(1.f + erff(v1*0.70710678118654752f));
                    __half2 hv; hv.x = __float2half_rn(v0); hv.y = __float2half_rn(v1);
                    *(__half2*)(Ch + (size_t)row*N + col) = hv;
                } else {
                    if (EPI == 2){
                        v0 += bias[col]   + res[(size_t)row*N + col];
                        v1 += bias[col+1] + res[(size_t)row*N + col+1];
                    }
                    float2 v; v.x = v0; v.y = v1;
                    *(float2*)(C + (size_t)row*N + col) = v;
                }
            }
        }
    }
}

// ---------------- dt / dA from fp16 xn (exact fp32 dot, fp32 weights) ----------------
__global__ void dtda_kernel(const float* __restrict__ in_w,
                            const float* __restrict__ dt_bias,
                            const float* __restrict__ A_log){
    int row = blockIdx.x*16 + (threadIdx.x >> 4);
    int h = threadIdx.x & 15;
    const __half* xr = g_xn + (size_t)row*DMODEL;
    const float* wc = in_w + 2176 + h;
    float acc = dt_bias[h];
    #pragma unroll 8
    for (int k = 0; k < DMODEL; k++)
        acc += __half2float(xr[k]) * wc[(size_t)k*DPROJ];
    float dt = (acc > 20.f) ? acc : log1pf(__expf(acc));
    float dA = __expf(-__expf(A_log[h]) * dt);
    int b = row >> 12, t = row & (SEQL-1);
    size_t i0 = ((size_t)(b*2+0)*SEQL + t)*NHEADS + h;
    size_t i1 = ((size_t)(b*2+1)*SEQL + (SEQL-1-t))*NHEADS + h;
    g_dt[i0] = dt; g_dA[i0] = dA;
    g_dt[i1] = dt; g_dA[i1] = dA;
}

// ---------------- selective scan w/ fused conv+silu ----------------
// 128 CTAs: (b, d, h, half). CTA: 32 headdim rows x 64 states. CHUNK=32.
#define CHUNK 32
#define NCHUNK (SEQL/CHUNK)
#define NCH 160              // 32 x-chans + 64 B + 64 C
#define RROWS (CHUNK + DCONV - 1)   // 35
// dynamic smem floats: sraw 2*35*160=11200, sconv 32*160=5120, scw 640, scb 160, sdt 64, sdA 64
#define SC_SRAW 0
#define SC_SCONV (2*RROWS*NCH)
#define SC_SCW   (SC_SCONV + CHUNK*NCH)
#define SC_SCB   (SC_SCW + 4*NCH)
#define SC_SDT   (SC_SCB + NCH)
#define SC_SDA   (SC_SDT + 2*CHUNK)
#define SC_TOTAL (SC_SDA + 2*CHUNK)
#define SC_BYTES (SC_TOTAL*4)

__global__ __launch_bounds__(256) void scan2_kernel(const float* __restrict__ Dh,
                                                    const float* __restrict__ cw,
                                                    const float* __restrict__ cb){
    extern __shared__ float ssm[];
    float* sraw  = ssm + SC_SRAW;    // [2][RROWS][NCH]
    float* sconv = ssm + SC_SCONV;   // [CHUNK][NCH]
    float* scw   = ssm + SC_SCW;     // [4][NCH]
    float* scb   = ssm + SC_SCB;     // [NCH]
    float* sdt   = ssm + SC_SDT;     // [2][CHUNK]
    float* sdA   = ssm + SC_SDA;     // [2][CHUNK]

    int bx = blockIdx.x;            // 0..127
    int half = bx & 1, h = (bx >> 1) & 15, d = (bx >> 5) & 1, b = bx >> 6;
    int tid = threadIdx.x;
    int p = tid >> 3, q = tid & 7;

    for (int ch = tid; ch < NCH; ch += 256){
        int cc = ch < 32 ? h*64 + half*32 + ch
               : (ch < 96 ? 1024 + (ch-32) : 1088 + (ch-96));
        scb[ch] = cb[cc];
        #pragma unroll
        for (int k=0;k<4;k++) scw[k*NCH + ch] = cw[k*CONVDIM + cc];
    }
    // zero boundary rows (u<0) of buffer 0
    for (int j = tid; j < 3*NCH; j += 256) sraw[j] = 0.f;
    __syncthreads();

    const float* zxb = g_zx + (size_t)b*SEQL*DPROJ_PAD;
    const float* dtb = g_dt + ((size_t)(b*2+d))*SEQL*NHEADS + h;
    const float* dab = g_dA + ((size_t)(b*2+d))*SEQL*NHEADS + h;
    float* ybase = g_y + ((size_t)(b*2+d))*SEQL*DINNER;
    int ycol = h*HEADDIM + half*32 + p;

    float hreg[8];
    #pragma unroll
    for (int i=0;i<8;i++) hreg[i] = 0.f;
    float Dhh = Dh[h];

    auto issue = [&](int c, int sbuf){
        int s0 = c*CHUNK;
        float* dst = sraw + sbuf*RROWS*NCH;
        #pragma unroll
        for (int it=0; it<6; it++){
            int j = tid + it*256;            // 1400 = RROWS*40 cp16 ops
            if (j < RROWS*40){
                int r = j / 40, seg = j % 40;
                int off = seg*4;
                int u = s0 - 3 + r;
                if (u >= 0){
                    int t = d ? (SEQL-1-u) : u;
                    const float* rowp = zxb + (size_t)t*DPROJ_PAD;
                    const float* src;
                    if (off < 32)      src = rowp + 1024 + h*64 + half*32 + off;
                    else if (off < 96) src = rowp + 2048 + (off-32);
                    else               src = rowp + 2112 + (off-96);
                    cp16(&dst[r*NCH + off], src);
                }
            }
        }
        if (tid < CHUNK)            cp4(&sdt[sbuf*CHUNK + tid],         dtb + (size_t)(s0+tid)*NHEADS);
        else if (tid < 2*CHUNK)     cp4(&sdA[sbuf*CHUNK + tid-CHUNK],   dab + (size_t)(s0+tid-CHUNK)*NHEADS);
        asm volatile("cp.async.commit_group;\n");
    };

    issue(0, 0);
    for (int c=0;c<NCHUNK;c++){
        int cur = c & 1, nxt = cur ^ 1;
        asm volatile("cp.async.wait_group 0;\n");
        __syncthreads();
        if (c+1 < NCHUNK) issue(c+1, nxt);
        // conv + silu (float4): CHUNK*NCH/4 = 1280 float4 outputs
        const float* rawc = sraw + cur*RROWS*NCH;
        #pragma unroll
        for (int it=0; it<5; it++){
            int j = tid + it*256;            // 0..1279
            int st = j / 40, c4 = j - st*40;
            float4 a = *(const float4*)&scb[c4*4];
            #pragma unroll
            for (int k=0;k<4;k++){
                float4 w4 = *(const float4*)&scw[k*NCH + c4*4];
                float4 r4 = *(const float4*)&rawc[(st+k)*NCH + c4*4];
                a.x += w4.x*r4.x; a.y += w4.y*r4.y; a.z += w4.z*r4.z; a.w += w4.w*r4.w;
            }
            a.x = siluf(a.x); a.y = siluf(a.y); a.z = siluf(a.z); a.w = siluf(a.w);
            *(float4*)&sconv[st*NCH + c4*4] = a;
        }
        __syncthreads();
        #pragma unroll 4
        for (int k=0;k<CHUNK;k++){
            const float* row = sconv + k*NCH;
            float dt = sdt[cur*CHUNK + k], dA = sdA[cur*CHUNK + k];
            float xh = row[p];
            float dtx = dt*xh;
            const float4* Bp4 = (const float4*)(row + 32 + q*8);
            const float4* Cp4 = (const float4*)(row + 96 + q*8);
            float4 b0 = Bp4[0], b1 = Bp4[1];
            float4 c0 = Cp4[0], c1 = Cp4[1];
            float bv[8] = {b0.x,b0.y,b0.z,b0.w,b1.x,b1.y,b1.z,b1.w};
            float cv[8] = {c0.x,c0.y,c0.z,c0.w,c1.x,c1.y,c1.z,c1.w};
            float acc = 0.f;
            #pragma unroll
            for (int i=0;i<8;i++){
                hreg[i] = hreg[i]*dA + dtx*bv[i];
                acc += hreg[i]*cv[i];
            }
            acc += __shfl_xor_sync(0xffffffffu, acc, 1);
            acc += __shfl_xor_sync(0xffffffffu, acc, 2);
            acc += __shfl_xor_sync(0xffffffffu, acc, 4);
            if (q == 0){
                int s = c*CHUNK + k;
                int t = d ? (SEQL-1-s) : s;
                ybase[(size_t)t*DINNER + ycol] = acc + Dhh*xh;
            }
        }
    }
}

// ---------------- gate (silu(z)), per-direction RMS norm, combine -> fp16 ----------------
__global__ void gate_kernel(const float* __restrict__ mw){
    int row = blockIdx.x;
    int b = row >> 12, t = row & (SEQL-1);
    int c = threadIdx.x * 4;
    const float4 zz4 = *(const float4*)(g_zx + (size_t)row*DPROJ_PAD + c);
    const float4 y04 = *(const float4*)(g_y + ((size_t)(b*2+0)*SEQL + t)*DINNER + c);
    const float4 y14 = *(const float4*)(g_y + ((size_t)(b*2+1)*SEQL + t)*DINNER + c);
    float g0[4], g1[4];
    float z_[4] = {zz4.x, zz4.y, zz4.z, zz4.w};
    float a0[4] = {y04.x, y04.y, y04.z, y04.w};
    float a1[4] = {y14.x, y14.y, y14.z, y14.w};
    float ss0 = 0.f, ss1 = 0.f;
    #pragma unroll
    for (int j=0;j<4;j++){
        float sz = siluf(z_[j]);
        g0[j] = a0[j]*sz; g1[j] = a1[j]*sz;
        ss0 += g0[j]*g0[j]; ss1 += g1[j]*g1[j];
    }
    #pragma unroll
    for (int o=16;o;o>>=1){
        ss0 += __shfl_xor_sync(0xffffffffu, ss0, o);
        ss1 += __shfl_xor_sync(0xffffffffu, ss1, o);
    }
    __shared__ float red[16];
    int wid = threadIdx.x >> 5, lane = threadIdx.x & 31;
    if (lane == 0){ red[wid] = ss0; red[8+wid] = ss1; }
    __syncthreads();
    if (threadIdx.x == 0){
        float a=0.f, bb=0.f;
        #pragma unroll
        for (int w=0;w<8;w++){ a += red[w]; bb += red[8+w]; }
        red[0] = a; red[8] = bb;
    }
    __syncthreads();
    float r0 = rsqrtf(red[0]*(1.f/DINNER) + EPS);
    float r1 = rsqrtf(red[8]*(1.f/DINNER) + EPS);
    __half2 h0, h1;
    h0.x = __float2half_rn((g0[0]*r0 + g1[0]*r1) * mw[c+0]);
    h0.y = __float2half_rn((g0[1]*r0 + g1[1]*r1) * mw[c+1]);
    h1.x = __float2half_rn((g0[2]*r0 + g1[2]*r1) * mw[c+2]);
    h1.y = __float2half_rn((g0[3]*r0 + g1[3]*r1) * mw[c+3]);
    __half2* go = (__half2*)(g_g + (size_t)row*DINNER + c);
    go[0] = h0; go[1] = h1;
}

// ---------------- launch ----------------
extern "C" void kernel_launch(void* const* d_in, const int* in_sizes, int n_in,
                              void* d_out, int out_size)
{
    const float* x        = (const float*)d_in[0];
    const float* nin_w    = (const float*)d_in[1];
    const float* nin_b    = (const float*)d_in[2];
    const float* nout_w   = (const float*)d_in[3];
    const float* nout_b   = (const float*)d_in[4];
    const float* in_w     = (const float*)d_in[5];
    const float* conv_w   = (const float*)d_in[6];
    const float* conv_b   = (const float*)d_in[7];
    const float* dt_bias  = (const float*)d_in[8];
    const float* A_log    = (const float*)d_in[9];
    const float* D_h      = (const float*)d_in[10];
    const float* mnorm_w  = (const float*)d_in[11];
    const float* out_w    = (const float*)d_in[12];
    const float* ff_w1    = (const float*)d_in[13];
    const float* ff_b1    = (const float*)d_in[14];
    const float* ff_w2    = (const float*)d_in[15];
    const float* ff_b2    = (const float*)d_in[16];
    float* out = (float*)d_out;

    float *p_zx, *p_mid;
    __half *p_xn, *p_g, *p_m, *p_ff1;
    __half *p_inwT, *p_outwT, *p_ff1T, *p_ff2T;
    cudaGetSymbolAddress((void**)&p_xn,   g_xn);
    cudaGetSymbolAddress((void**)&p_zx,   g_zx);
    cudaGetSymbolAddress((void**)&p_g,    g_g);
    cudaGetSymbolAddress((void**)&p_mid,  g_mid);
    cudaGetSymbolAddress((void**)&p_m,    g_m);
    cudaGetSymbolAddress((void**)&p_ff1,  g_ff1);
    cudaGetSymbolAddress((void**)&p_inwT, g_inwT);
    cudaGetSymbolAddress((void**)&p_outwT,g_outwT);
    cudaGetSymbolAddress((void**)&p_ff1T, g_ff1T);
    cudaGetSymbolAddress((void**)&p_ff2T, g_ff2T);

    cudaFuncSetAttribute(mma_gemm<0>, cudaFuncAttributeMaxDynamicSharedMemorySize, GSMEM_BYTES);
    cudaFuncSetAttribute(mma_gemm<1>, cudaFuncAttributeMaxDynamicSharedMemorySize, GSMEM_BYTES);
    cudaFuncSetAttribute(mma_gemm<2>, cudaFuncAttributeMaxDynamicSharedMemorySize, GSMEM_BYTES);
    cudaFuncSetAttribute(scan2_kernel, cudaFuncAttributeMaxDynamicSharedMemorySize, SC_BYTES);

    // 1. prep: all weight transposes + input layernorm
    prep_kernel<<<4736, 256>>>(in_w, out_w, ff_w1, ff_w2, x, nin_w, nin_b);

    // 2. in-proj: xn[8192,512] @ inwT[2304,512]^T -> zx[8192,2304]
    mma_gemm<0><<<dim3(DPROJ_PAD/128, ROWS/128), 256, GSMEM_BYTES>>>(
        p_xn, p_inwT, p_zx, nullptr, DMODEL, DPROJ_PAD, nullptr, nullptr);

    // 3. dt/dA (exact fp32)
    dtda_kernel<<<ROWS/16, 256>>>(in_w, dt_bias, A_log);

    // 4. scan with fused conv+silu  (<- ncu capture slot)
    scan2_kernel<<<128, 256, SC_BYTES>>>(D_h, conv_w, conv_b);

    // 5. gate + per-dir rmsnorm + combine (fp16 out)
    gate_kernel<<<ROWS, 256>>>(mnorm_w);

    // 6. out-proj: g[8192,1024] @ outwT[512,1024]^T -> mid[8192,512]
    mma_gemm<0><<<dim3(DMODEL/128, ROWS/128), 256, GSMEM_BYTES>>>(
        p_g, p_outwT, p_mid, nullptr, DINNER, DMODEL, nullptr, nullptr);

    // 7. layernorm out (fp16)
    ln_kernel<<<ROWS/8, 256>>>(p_mid, nout_w, nout_b, p_m);

    // 8. FF1 + gelu -> fp16
    mma_gemm<1><<<dim3(DFF/128, ROWS/128), 256, GSMEM_BYTES>>>(
        p_m, p_ff1T, nullptr, p_ff1, DMODEL, DFF, ff_b1, nullptr);

    // 9. FF2 + bias + residual(x)
    mma_gemm<2><<<dim3(DMODEL/128, ROWS/128), 256, GSMEM_BYTES>>>(
        p_ff1, p_ff2T, out, nullptr, DFF, DMODEL, ff_b2, x);
}